// round 7
// baseline (speedup 1.0000x reference)
#include <cuda_runtime.h>
#include <cuda_bf16.h>
#include <math.h>

#define BB 2
#define TT 2048
#define CC 1024
#define HH 16
#define BT (BB*TT)   // 4096

typedef unsigned int u32;
typedef unsigned long long u64;

// ---------------------------------------------------------------------------
// Scratch (__device__ globals; no allocations allowed)
// ---------------------------------------------------------------------------
__device__ __align__(256) __nv_bfloat16 g_xhi[(size_t)BT * CC];
__device__ __align__(256) __nv_bfloat16 g_xlo[(size_t)BT * CC];
__device__ __align__(256) __nv_bfloat16 g_wqhi[(size_t)3 * CC * CC];
__device__ __align__(256) __nv_bfloat16 g_wqlo[(size_t)3 * CC * CC];
__device__ __align__(256) __nv_bfloat16 g_wphi[(size_t)CC * CC];
__device__ __align__(256) __nv_bfloat16 g_wplo[(size_t)CC * CC];
__device__ __align__(256) __nv_bfloat16 g_qhi[(size_t)BT * 3 * CC];
__device__ __align__(256) __nv_bfloat16 g_qlo[(size_t)BT * 3 * CC];
__device__ __align__(256) __nv_bfloat16 g_ahi[(size_t)BT * CC];
__device__ __align__(256) __nv_bfloat16 g_alo[(size_t)BT * CC];

// ---------------------------------------------------------------------------
// PTX helpers
// ---------------------------------------------------------------------------
__device__ __forceinline__ u32 s2u(const void* p) {
    u32 a;
    asm("{ .reg .u64 t; cvta.to.shared.u64 t, %1; cvt.u32.u64 %0, t; }"
        : "=r"(a) : "l"(p));
    return a;
}
__device__ __forceinline__ void cpa16(u32 dst, const void* src) {
    asm volatile("cp.async.cg.shared.global [%0], [%1], 16;" :: "r"(dst), "l"(src));
}
#define CP_COMMIT() asm volatile("cp.async.commit_group;" ::: "memory")
#define CP_WAIT1()  asm volatile("cp.async.wait_group 1;" ::: "memory")
__device__ __forceinline__ void ldsm4(u32* r, u32 addr) {
    asm volatile("ldmatrix.sync.aligned.m8n8.x4.shared.b16 {%0,%1,%2,%3}, [%4];"
                 : "=r"(r[0]), "=r"(r[1]), "=r"(r[2]), "=r"(r[3]) : "r"(addr));
}
__device__ __forceinline__ void ldsm4t(u32* r, u32 addr) {
    asm volatile("ldmatrix.sync.aligned.m8n8.x4.trans.shared.b16 {%0,%1,%2,%3}, [%4];"
                 : "=r"(r[0]), "=r"(r[1]), "=r"(r[2]), "=r"(r[3]) : "r"(addr));
}
__device__ __forceinline__ void ldsm2(u32* r, u32 addr) {
    asm volatile("ldmatrix.sync.aligned.m8n8.x2.shared.b16 {%0,%1}, [%2];"
                 : "=r"(r[0]), "=r"(r[1]) : "r"(addr));
}
__device__ __forceinline__ void mma16816(float* d, const u32* a, const u32* b) {
    asm volatile(
        "mma.sync.aligned.m16n8k16.row.col.f32.bf16.bf16.f32 "
        "{%0,%1,%2,%3}, {%4,%5,%6,%7}, {%8,%9}, {%0,%1,%2,%3};"
        : "+f"(d[0]), "+f"(d[1]), "+f"(d[2]), "+f"(d[3])
        : "r"(a[0]), "r"(a[1]), "r"(a[2]), "r"(a[3]), "r"(b[0]), "r"(b[1]));
}
// Split (a,b) fp32 pair into packed bf16 hi-word and residual lo-word.
__device__ __forceinline__ void split2(float a, float b, u32& hw, u32& lw) {
    asm("cvt.rn.bf16x2.f32 %0, %1, %2;" : "=r"(hw) : "f"(b), "f"(a));
    float ha = __uint_as_float(hw << 16);
    float hb = __uint_as_float(hw & 0xFFFF0000u);
    float la = a - ha, lb = b - hb;
    asm("cvt.rn.bf16x2.f32 %0, %1, %2;" : "=r"(lw) : "f"(lb), "f"(la));
}
// softplus: max(x,0) + ln(1+e^{-|x|}); ln via ln1.5 + deg-9 series in y=(2e-1)/3
__device__ __forceinline__ float softplus_f(float x) {
    float e = __expf(-fabsf(x));
    float y = fmaf(e, 0.6666666667f, -0.3333333333f);
    float q = 0.1111111111f;
    q = fmaf(q, y, -0.125f);
    q = fmaf(q, y, 0.1428571429f);
    q = fmaf(q, y, -0.1666666667f);
    q = fmaf(q, y, 0.2f);
    q = fmaf(q, y, -0.25f);
    q = fmaf(q, y, 0.3333333333f);
    q = fmaf(q, y, -0.5f);
    q = fmaf(q, y, 1.0f);
    return fmaxf(x, 0.f) + fmaf(q, y, 0.4054651081f);
}

// ---------------------------------------------------------------------------
// fp32 -> bf16 hi/lo split kernel
// ---------------------------------------------------------------------------
__global__ __launch_bounds__(256)
void split_bf16(const float4* __restrict__ src, uint2* __restrict__ hi,
                uint2* __restrict__ lo, int n4) {
    int i = blockIdx.x * blockDim.x + threadIdx.x;
    if (i >= n4) return;
    float4 v = src[i];
    u32 h0, l0, h1, l1;
    split2(v.x, v.y, h0, l0);
    split2(v.z, v.w, h1, l1);
    hi[i] = make_uint2(h0, h1);
    lo[i] = make_uint2(l0, l1);
}

// ---------------------------------------------------------------------------
// HMMA GEMM: C[M,N] = (Ahi+Alo)[M,K] @ (Whi+Wlo)[N,K]^T
// 128x128x32 tile, 8 warps, 3-stage pipeline, ONE sync/iter, 2 CTAs/SM.
// ---------------------------------------------------------------------------
#define GM_STAGE 32768
#define GM_SMEM_BYTES (3 * GM_STAGE)

__device__ __forceinline__ u32 sw_off(int r, int c) {
    return (u32)(((r << 2) + (c ^ ((r >> 1) & 3))) << 4);
}

__device__ __forceinline__ void load_tile_g(
    u32 sbuf, int tid,
    const __nv_bfloat16* __restrict__ Ah, const __nv_bfloat16* __restrict__ Al,
    const __nv_bfloat16* __restrict__ Wh, const __nv_bfloat16* __restrict__ Wl,
    int bm, int bn, int K, int k0)
{
    #pragma unroll
    for (int q = 0; q < 2; q++) {
        int idx = tid + q * 256;
        int r = idx >> 2;
        int c = idx & 3;
        u32 so = sw_off(r, c);
        size_t ga = (size_t)(bm + r) * K + k0 + c * 8;
        size_t gw = (size_t)(bn + r) * K + k0 + c * 8;
        cpa16(sbuf +         so, Ah + ga);
        cpa16(sbuf +  8192 + so, Al + ga);
        cpa16(sbuf + 16384 + so, Wh + gw);
        cpa16(sbuf + 24576 + so, Wl + gw);
    }
}

__global__ __launch_bounds__(256, 2)
void gemm_mma(const __nv_bfloat16* __restrict__ Ahi, const __nv_bfloat16* __restrict__ Alo,
              const __nv_bfloat16* __restrict__ Whi, const __nv_bfloat16* __restrict__ Wlo,
              const float* __restrict__ bias, float* __restrict__ Cf,
              __nv_bfloat16* __restrict__ Oh, __nv_bfloat16* __restrict__ Ol,
              int N, int K) {
    extern __shared__ char smem[];
    const u32 sb = s2u(smem);
    const int tid = threadIdx.x;
    const int wid = tid >> 5, lane = tid & 31;
    const int bm = blockIdx.y * 128, bn = blockIdx.x * 128;
    const int wm = (wid >> 2) * 64;
    const int wn = (wid & 3) * 32;

    float acc[4][4][4];
    #pragma unroll
    for (int i = 0; i < 4; i++)
        #pragma unroll
        for (int j = 0; j < 4; j++)
            #pragma unroll
            for (int u = 0; u < 4; u++) acc[i][j][u] = 0.f;

    const int NIT = K / 32;   // 32 (K=1024)

    load_tile_g(sb, tid, Ahi, Alo, Whi, Wlo, bm, bn, K, 0);
    CP_COMMIT();
    load_tile_g(sb + GM_STAGE, tid, Ahi, Alo, Whi, Wlo, bm, bn, K, 32);
    CP_COMMIT();

    const int arow = lane & 15;
    const int akh  = lane >> 4;
    const int brow = lane & 7;
    const int bkh  = (lane >> 3) & 1;

    int cur = 0;   // stage holding iter 'it'
    for (int it = 0; it < NIT; it++) {
        CP_WAIT1();          // group(it) complete (issued 2 iters back)
        __syncthreads();     // visible to all; stage (cur+2)%3 free for reuse
        if (it + 2 < NIT) {
            int ps = cur + 2; if (ps >= 3) ps -= 3;
            load_tile_g(sb + ps * GM_STAGE, tid, Ahi, Alo, Whi, Wlo,
                        bm, bn, K, (it + 2) * 32);
        }
        CP_COMMIT();         // always commit: keeps group numbering exact

        const u32 bb = sb + cur * GM_STAGE;
        #pragma unroll
        for (int kk2 = 0; kk2 < 4; kk2 += 2) {
            u32 ah[4][4], al[4][4];
            #pragma unroll
            for (int i = 0; i < 4; i++) {
                u32 off = sw_off(wm + i * 16 + arow, kk2 + akh);
                ldsm4(ah[i], bb + off);
                ldsm4(al[i], bb + 8192 + off);
            }
            u32 wh[4][2], wl[4][2];
            #pragma unroll
            for (int j = 0; j < 4; j++) {
                u32 off = sw_off(wn + j * 8 + brow, kk2 + bkh);
                ldsm2(wh[j], bb + 16384 + off);
                ldsm2(wl[j], bb + 24576 + off);
            }
            #pragma unroll
            for (int i = 0; i < 4; i++)
                #pragma unroll
                for (int j = 0; j < 4; j++) {
                    mma16816(acc[i][j], ah[i], wh[j]);
                    mma16816(acc[i][j], ah[i], wl[j]);
                    mma16816(acc[i][j], al[i], wh[j]);
                }
        }
        cur = (cur == 2) ? 0 : cur + 1;
    }

    const int g = lane >> 2, tc = lane & 3;
    #pragma unroll
    for (int i = 0; i < 4; i++) {
        #pragma unroll
        for (int j = 0; j < 4; j++) {
            const int col = bn + wn + j * 8 + tc * 2;
            const size_t r0 = (size_t)(bm + wm + i * 16 + g) * N + col;
            const size_t r1 = r0 + (size_t)8 * N;
            if (Cf) {
                float b0 = bias ? bias[col] : 0.f;
                float b1 = bias ? bias[col + 1] : 0.f;
                *(float2*)&Cf[r0] = make_float2(acc[i][j][0] + b0, acc[i][j][1] + b1);
                *(float2*)&Cf[r1] = make_float2(acc[i][j][2] + b0, acc[i][j][3] + b1);
            } else {
                u32 hw, lw;
                split2(acc[i][j][0], acc[i][j][1], hw, lw);
                *(u32*)&Oh[r0] = hw; *(u32*)&Ol[r0] = lw;
                split2(acc[i][j][2], acc[i][j][3], hw, lw);
                *(u32*)&Oh[r1] = hw; *(u32*)&Ol[r1] = lw;
            }
        }
    }
}

// ---------------------------------------------------------------------------
// HMMA sp2norm attention. 3 KV buffers (Q smem recycled as buf2),
// ONE sync per KV block, prefetch distance 2, 2 CTAs/SM.
// ---------------------------------------------------------------------------
#define AT_STAGE 32768
#define AT_SMEM_BYTES (3 * AT_STAGE)

__device__ __forceinline__ void load_kv_a(
    u32 dst, int tid, const __nv_bfloat16* __restrict__ qhi,
    const __nv_bfloat16* __restrict__ qlo, size_t kvbase)
{
    #pragma unroll
    for (int q = 0; q < 2; q++) {
        int slot = tid + q * 256;
        int r = slot >> 3;
        int c = slot & 7;
        u32 so = (u32)(r * 128 + ((c ^ (r & 7)) << 4));
        size_t gk = kvbase + (size_t)r * (3 * CC) + CC + c * 8;
        size_t gv = gk + CC;
        cpa16(dst +         so, qhi + gk);
        cpa16(dst +  8192 + so, qlo + gk);
        cpa16(dst + 16384 + so, qhi + gv);
        cpa16(dst + 24576 + so, qlo + gv);
    }
}

__global__ __launch_bounds__(256, 2)
void attn_mma(const __nv_bfloat16* __restrict__ qhi, const __nv_bfloat16* __restrict__ qlo,
              __nv_bfloat16* __restrict__ ahi, __nv_bfloat16* __restrict__ alo) {
    extern __shared__ char smem[];
    const u32 sb = s2u(smem);
    const int tid = threadIdx.x;
    const int wid = tid >> 5, lane = tid & 31;
    const int g = lane >> 2, tc = lane & 3;
    const int qb = gridDim.x - 1 - blockIdx.x;
    const int h = blockIdx.y, b = blockIdx.z;

    const size_t qbase = ((size_t)(b * TT + qb * 128)) * (3 * CC) + h * 64;

    // group g0: Q (into buf2 region, hi at +0, lo at +16K) and KV block 0 (buf0)
    #pragma unroll
    for (int q = 0; q < 4; q++) {
        int slot = tid + q * 256;
        int r = slot >> 3;
        int c = slot & 7;
        u32 so = (u32)(r * 128 + ((c ^ (r & 7)) << 4));
        size_t gq = qbase + (size_t)r * (3 * CC) + c * 8;
        cpa16(sb + 2 * AT_STAGE +         so, qhi + gq);
        cpa16(sb + 2 * AT_STAGE + 16384 + so, qlo + gq);
    }
    load_kv_a(sb, tid, qhi, qlo, ((size_t)(b * TT)) * (3 * CC) + h * 64);
    CP_COMMIT();
    // group g1: KV block 1 (buf1)
    load_kv_a(sb + AT_STAGE, tid, qhi, qlo,
              ((size_t)(b * TT + 64)) * (3 * CC) + h * 64);
    CP_COMMIT();

    CP_WAIT1();          // g0 (Q + KV0) done
    __syncthreads();

    // Extract Q fragments, then free buf2 for KV reuse
    u32 qh[4][4], ql[4][4];
    {
        const int row = 16 * wid + (lane & 15);
        const int ckb = lane >> 4;
        #pragma unroll
        for (int t = 0; t < 4; t++) {
            int ck = 2 * t + ckb;
            u32 off = (u32)(row * 128 + ((ck ^ (row & 7)) << 4));
            ldsm4(qh[t], sb + 2 * AT_STAGE + off);
            ldsm4(ql[t], sb + 2 * AT_STAGE + 16384 + off);
        }
    }

    float o[8][4];
    #pragma unroll
    for (int v = 0; v < 8; v++)
        #pragma unroll
        for (int u = 0; u < 4; u++) o[v][u] = 0.f;
    float rsq0 = 0.f, rsq1 = 0.f;

    const int qg0 = qb * 128 + 16 * wid + g;
    const int jmax = 2 * qb + 1;

    int cur = 0;
    for (int j = 0; j <= jmax; j++) {
        CP_WAIT1();        // group(j) complete
        __syncthreads();   // KV(j) visible; buf (cur+2)%3 free (also guards Q reuse at j=0)
        if (j + 2 <= jmax) {
            int ps = cur + 2; if (ps >= 3) ps -= 3;
            load_kv_a(sb + ps * AT_STAGE, tid, qhi, qlo,
                      ((size_t)(b * TT + (j + 2) * 64)) * (3 * CC) + h * 64);
        }
        CP_COMMIT();

        const u32 bb = sb + cur * AT_STAGE;
        cur = (cur == 2) ? 0 : cur + 1;

        const bool dg = (j >= 2 * qb);
        const bool act = !(dg && (j * 64 > qb * 128 + 16 * wid + 15));
        if (act) {
            float s[8][4];
            #pragma unroll
            for (int v = 0; v < 8; v++)
                #pragma unroll
                for (int u = 0; u < 4; u++) s[v][u] = 0.f;

            const int rowK = (lane & 7) + ((lane >> 4) << 3);
            const int ckK  = (lane >> 3) & 1;
            #pragma unroll
            for (int t = 0; t < 4; t++) {
                #pragma unroll
                for (int u = 0; u < 4; u++) {
                    int rK = 16 * u + rowK;
                    int ck = 2 * t + ckK;
                    u32 off = (u32)(rK * 128 + ((ck ^ (rK & 7)) << 4));
                    u32 kh[4], kl[4];
                    ldsm4(kh, bb + off);
                    ldsm4(kl, bb + 8192 + off);
                    mma16816(s[2*u],   qh[t], kh);
                    mma16816(s[2*u],   ql[t], kh);
                    mma16816(s[2*u],   qh[t], kl);
                    mma16816(s[2*u+1], qh[t], kh + 2);
                    mma16816(s[2*u+1], ql[t], kh + 2);
                    mma16816(s[2*u+1], qh[t], kl + 2);
                }
            }

            const int rowVb = (lane & 7) + (((lane >> 3) & 1) << 3);
            const int cvb = lane >> 4;
            #pragma unroll
            for (int t = 0; t < 4; t++) {
                float w0 = softplus_f(s[2*t][0]   * 0.125f);
                float w1 = softplus_f(s[2*t][1]   * 0.125f);
                float w2 = softplus_f(s[2*t][2]   * 0.125f);
                float w3 = softplus_f(s[2*t][3]   * 0.125f);
                float w4 = softplus_f(s[2*t+1][0] * 0.125f);
                float w5 = softplus_f(s[2*t+1][1] * 0.125f);
                float w6 = softplus_f(s[2*t+1][2] * 0.125f);
                float w7 = softplus_f(s[2*t+1][3] * 0.125f);
                if (dg) {
                    int kg = j * 64 + 16 * t + 2 * tc;
                    int q0 = qg0, q1 = qg0 + 8;
                    if (kg     > q0) w0 = 0.f;
                    if (kg + 1 > q0) w1 = 0.f;
                    if (kg     > q1) w2 = 0.f;
                    if (kg + 1 > q1) w3 = 0.f;
                    if (kg + 8 > q0) w4 = 0.f;
                    if (kg + 9 > q0) w5 = 0.f;
                    if (kg + 8 > q1) w6 = 0.f;
                    if (kg + 9 > q1) w7 = 0.f;
                }
                rsq0 = fmaf(w0, w0, rsq0); rsq0 = fmaf(w1, w1, rsq0);
                rsq0 = fmaf(w4, w4, rsq0); rsq0 = fmaf(w5, w5, rsq0);
                rsq1 = fmaf(w2, w2, rsq1); rsq1 = fmaf(w3, w3, rsq1);
                rsq1 = fmaf(w6, w6, rsq1); rsq1 = fmaf(w7, w7, rsq1);

                u32 wh[4], wl[4];
                split2(w0, w1, wh[0], wl[0]);
                split2(w2, w3, wh[1], wl[1]);
                split2(w4, w5, wh[2], wl[2]);
                split2(w6, w7, wh[3], wl[3]);

                const int rV = 16 * t + rowVb;
                #pragma unroll
                for (int v = 0; v < 4; v++) {
                    int cv = 2 * v + cvb;
                    u32 off = (u32)(rV * 128 + ((cv ^ (rV & 7)) << 4));
                    u32 vh[4], vl[4];
                    ldsm4t(vh, bb + 16384 + off);
                    ldsm4t(vl, bb + 24576 + off);
                    mma16816(o[2*v],   wh, vh);
                    mma16816(o[2*v],   wl, vh);
                    mma16816(o[2*v],   wh, vl);
                    mma16816(o[2*v+1], wh, vh + 2);
                    mma16816(o[2*v+1], wl, vh + 2);
                    mma16816(o[2*v+1], wh, vl + 2);
                }
            }
        }
    }

    rsq0 += __shfl_xor_sync(0xffffffffu, rsq0, 1);
    rsq0 += __shfl_xor_sync(0xffffffffu, rsq0, 2);
    rsq1 += __shfl_xor_sync(0xffffffffu, rsq1, 1);
    rsq1 += __shfl_xor_sync(0xffffffffu, rsq1, 2);
    const float inv0 = rsqrtf(rsq0);
    const float inv1 = rsqrtf(rsq1);

    const size_t obase = (size_t)(b * TT + qg0) * CC + h * 64 + 2 * tc;
    #pragma unroll
    for (int v = 0; v < 8; v++) {
        u32 hw, lw;
        split2(o[v][0] * inv0, o[v][1] * inv0, hw, lw);
        *(u32*)&ahi[obase + 8 * v] = hw;
        *(u32*)&alo[obase + 8 * v] = lw;
        split2(o[v][2] * inv1, o[v][3] * inv1, hw, lw);
        *(u32*)&ahi[obase + 8 * (size_t)CC + 8 * v] = hw;
        *(u32*)&alo[obase + 8 * (size_t)CC + 8 * v] = lw;
    }
}

// ---------------------------------------------------------------------------
extern "C" void kernel_launch(void* const* d_in, const int* in_sizes, int n_in,
                              void* d_out, int out_size) {
    const float* x     = (const float*)d_in[0];
    const float* Wqkv  = (const float*)d_in[1];
    const float* Wproj = (const float*)d_in[2];
    const float* bproj = (const float*)d_in[3];
    float* out = (float*)d_out;

    __nv_bfloat16 *xhi, *xlo, *wqhi, *wqlo, *wphi, *wplo, *qhi, *qlo, *ahi, *alo;
    cudaGetSymbolAddress((void**)&xhi, g_xhi);
    cudaGetSymbolAddress((void**)&xlo, g_xlo);
    cudaGetSymbolAddress((void**)&wqhi, g_wqhi);
    cudaGetSymbolAddress((void**)&wqlo, g_wqlo);
    cudaGetSymbolAddress((void**)&wphi, g_wphi);
    cudaGetSymbolAddress((void**)&wplo, g_wplo);
    cudaGetSymbolAddress((void**)&qhi, g_qhi);
    cudaGetSymbolAddress((void**)&qlo, g_qlo);
    cudaGetSymbolAddress((void**)&ahi, g_ahi);
    cudaGetSymbolAddress((void**)&alo, g_alo);

    cudaFuncSetAttribute(gemm_mma, cudaFuncAttributeMaxDynamicSharedMemorySize,
                         GM_SMEM_BYTES);
    cudaFuncSetAttribute(attn_mma, cudaFuncAttributeMaxDynamicSharedMemorySize,
                         AT_SMEM_BYTES);

    int n4x = BT * CC / 4;
    int n4q = 3 * CC * CC / 4;
    int n4p = CC * CC / 4;
    split_bf16<<<(n4x + 255) / 256, 256>>>((const float4*)x, (uint2*)xhi, (uint2*)xlo, n4x);
    split_bf16<<<(n4q + 255) / 256, 256>>>((const float4*)Wqkv, (uint2*)wqhi, (uint2*)wqlo, n4q);
    split_bf16<<<(n4p + 255) / 256, 256>>>((const float4*)Wproj, (uint2*)wphi, (uint2*)wplo, n4p);

    // 1) QKV = x @ Wqkv^T -> bf16 hi/lo directly
    gemm_mma<<<dim3((3 * CC) / 128, BT / 128), 256, GM_SMEM_BYTES>>>(
        xhi, xlo, wqhi, wqlo, nullptr, nullptr, qhi, qlo, 3 * CC, CC);

    // 2) attention (causal sp2norm) -> bf16 hi/lo directly
    attn_mma<<<dim3(TT / 128, HH, BB), 256, AT_SMEM_BYTES>>>(qhi, qlo, ahi, alo);

    // 3) out = att @ Wproj^T + b (fp32)
    gemm_mma<<<dim3(CC / 128, BT / 128), 256, GM_SMEM_BYTES>>>(
        ahi, alo, wphi, wplo, bproj, out, nullptr, nullptr, CC, CC);
}

// round 8
// speedup vs baseline: 1.0161x; 1.0161x over previous
#include <cuda_runtime.h>
#include <cuda_bf16.h>
#include <math.h>

#define BB 2
#define TT 2048
#define CC 1024
#define HH 16
#define BT (BB*TT)   // 4096

typedef unsigned int u32;
typedef unsigned long long u64;

// ---------------------------------------------------------------------------
// Scratch (__device__ globals; no allocations allowed)
// ---------------------------------------------------------------------------
__device__ __align__(256) __nv_bfloat16 g_xhi[(size_t)BT * CC];
__device__ __align__(256) __nv_bfloat16 g_xlo[(size_t)BT * CC];
__device__ __align__(256) __nv_bfloat16 g_wqhi[(size_t)3 * CC * CC];
__device__ __align__(256) __nv_bfloat16 g_wqlo[(size_t)3 * CC * CC];
__device__ __align__(256) __nv_bfloat16 g_wphi[(size_t)CC * CC];
__device__ __align__(256) __nv_bfloat16 g_wplo[(size_t)CC * CC];
__device__ __align__(256) __nv_bfloat16 g_qhi[(size_t)BT * 3 * CC];
__device__ __align__(256) __nv_bfloat16 g_qlo[(size_t)BT * 3 * CC];
__device__ __align__(256) __nv_bfloat16 g_ahi[(size_t)BT * CC];
__device__ __align__(256) __nv_bfloat16 g_alo[(size_t)BT * CC];

// ---------------------------------------------------------------------------
// PTX helpers
// ---------------------------------------------------------------------------
__device__ __forceinline__ u32 s2u(const void* p) {
    u32 a;
    asm("{ .reg .u64 t; cvta.to.shared.u64 t, %1; cvt.u32.u64 %0, t; }"
        : "=r"(a) : "l"(p));
    return a;
}
__device__ __forceinline__ void cpa16(u32 dst, const void* src) {
    asm volatile("cp.async.cg.shared.global [%0], [%1], 16;" :: "r"(dst), "l"(src));
}
#define CP_COMMIT() asm volatile("cp.async.commit_group;" ::: "memory")
__device__ __forceinline__ void ldsm4(u32* r, u32 addr) {
    asm volatile("ldmatrix.sync.aligned.m8n8.x4.shared.b16 {%0,%1,%2,%3}, [%4];"
                 : "=r"(r[0]), "=r"(r[1]), "=r"(r[2]), "=r"(r[3]) : "r"(addr));
}
__device__ __forceinline__ void ldsm4t(u32* r, u32 addr) {
    asm volatile("ldmatrix.sync.aligned.m8n8.x4.trans.shared.b16 {%0,%1,%2,%3}, [%4];"
                 : "=r"(r[0]), "=r"(r[1]), "=r"(r[2]), "=r"(r[3]) : "r"(addr));
}
__device__ __forceinline__ void mma16816(float* d, const u32* a, const u32* b) {
    asm volatile(
        "mma.sync.aligned.m16n8k16.row.col.f32.bf16.bf16.f32 "
        "{%0,%1,%2,%3}, {%4,%5,%6,%7}, {%8,%9}, {%0,%1,%2,%3};"
        : "+f"(d[0]), "+f"(d[1]), "+f"(d[2]), "+f"(d[3])
        : "r"(a[0]), "r"(a[1]), "r"(a[2]), "r"(a[3]), "r"(b[0]), "r"(b[1]));
}
// Split (a,b) fp32 pair into packed bf16 hi-word and residual lo-word.
__device__ __forceinline__ void split2(float a, float b, u32& hw, u32& lw) {
    asm("cvt.rn.bf16x2.f32 %0, %1, %2;" : "=r"(hw) : "f"(b), "f"(a));
    float ha = __uint_as_float(hw << 16);
    float hb = __uint_as_float(hw & 0xFFFF0000u);
    float la = a - ha, lb = b - hb;
    asm("cvt.rn.bf16x2.f32 %0, %1, %2;" : "=r"(lw) : "f"(lb), "f"(la));
}
// softplus: max(x,0) + ln(1+e^{-|x|}); ln via ln1.5 + deg-9 series in y=(2e-1)/3
__device__ __forceinline__ float softplus_f(float x) {
    float e = __expf(-fabsf(x));
    float y = fmaf(e, 0.6666666667f, -0.3333333333f);
    float q = 0.1111111111f;
    q = fmaf(q, y, -0.125f);
    q = fmaf(q, y, 0.1428571429f);
    q = fmaf(q, y, -0.1666666667f);
    q = fmaf(q, y, 0.2f);
    q = fmaf(q, y, -0.25f);
    q = fmaf(q, y, 0.3333333333f);
    q = fmaf(q, y, -0.5f);
    q = fmaf(q, y, 1.0f);
    return fmaxf(x, 0.f) + fmaf(q, y, 0.4054651081f);
}

// ---------------------------------------------------------------------------
// fp32 -> bf16 hi/lo split kernel
// ---------------------------------------------------------------------------
__global__ __launch_bounds__(256)
void split_bf16(const float4* __restrict__ src, uint2* __restrict__ hi,
                uint2* __restrict__ lo, int n4) {
    int i = blockIdx.x * blockDim.x + threadIdx.x;
    if (i >= n4) return;
    float4 v = src[i];
    u32 h0, l0, h1, l1;
    split2(v.x, v.y, h0, l0);
    split2(v.z, v.w, h1, l1);
    hi[i] = make_uint2(h0, h1);
    lo[i] = make_uint2(l0, l1);
}

// ---------------------------------------------------------------------------
// HMMA GEMM: C[M,N] = (Ahi+Alo)[M,K] @ (Whi+Wlo)[N,K]^T
// CTA tile 256x128x32, 8 warps (4m x 2n), warp tile 64x64, 3-stage pipeline.
// Stage (48KB): Ahi[16K] Alo[16K] Whi[8K] Wlo[8K].
// ---------------------------------------------------------------------------
#define GM_STAGE 49152
#define GM_SMEM_BYTES (3 * GM_STAGE)

__device__ __forceinline__ u32 sw_off(int r, int c) {
    return (u32)(((r << 2) + (c ^ ((r >> 1) & 3))) << 4);
}

__device__ __forceinline__ void load_tile_g(
    u32 sbuf, int tid,
    const __nv_bfloat16* __restrict__ Ah, const __nv_bfloat16* __restrict__ Al,
    const __nv_bfloat16* __restrict__ Wh, const __nv_bfloat16* __restrict__ Wl,
    int bm, int bn, int K, int k0)
{
    #pragma unroll
    for (int q = 0; q < 4; q++) {          // A: 256 rows x 4 chunks
        int idx = tid + q * 256;
        int r = idx >> 2;
        int c = idx & 3;
        u32 so = sw_off(r, c);
        size_t ga = (size_t)(bm + r) * K + k0 + c * 8;
        cpa16(sbuf +         so, Ah + ga);
        cpa16(sbuf + 16384 + so, Al + ga);
    }
    #pragma unroll
    for (int q = 0; q < 2; q++) {          // W: 128 rows x 4 chunks
        int idx = tid + q * 256;
        int r = idx >> 2;
        int c = idx & 3;
        u32 so = sw_off(r, c);
        size_t gw = (size_t)(bn + r) * K + k0 + c * 8;
        cpa16(sbuf + 32768 + so, Wh + gw);
        cpa16(sbuf + 40960 + so, Wl + gw);
    }
}

__global__ __launch_bounds__(256, 1)
void gemm_mma(const __nv_bfloat16* __restrict__ Ahi, const __nv_bfloat16* __restrict__ Alo,
              const __nv_bfloat16* __restrict__ Whi, const __nv_bfloat16* __restrict__ Wlo,
              const float* __restrict__ bias, float* __restrict__ Cf,
              __nv_bfloat16* __restrict__ Oh, __nv_bfloat16* __restrict__ Ol,
              int N, int K) {
    extern __shared__ char smem[];
    const u32 sb = s2u(smem);
    const int tid = threadIdx.x;
    const int wid = tid >> 5, lane = tid & 31;
    const int bm = blockIdx.y * 256, bn = blockIdx.x * 128;
    const int wm = (wid >> 1) * 64;
    const int wn = (wid & 1) * 64;

    float acc[4][8][4];
    #pragma unroll
    for (int i = 0; i < 4; i++)
        #pragma unroll
        for (int j = 0; j < 8; j++)
            #pragma unroll
            for (int u = 0; u < 4; u++) acc[i][j][u] = 0.f;

    const int NIT = K / 32;

    load_tile_g(sb, tid, Ahi, Alo, Whi, Wlo, bm, bn, K, 0);
    CP_COMMIT();
    load_tile_g(sb + GM_STAGE, tid, Ahi, Alo, Whi, Wlo, bm, bn, K, 32);
    CP_COMMIT();

    const int arow = lane & 15;
    const int akh  = lane >> 4;
    // B ldsm x4 lane mapping: matrices (jp*2 + (lane>>4), k-chunk kk2+((lane>>3)&1))
    const int bj   = (lane >> 4) & 1;       // n-frag within pair
    const int bkc  = (lane >> 3) & 1;       // k-chunk half
    const int brow = lane & 7;

    int cur = 0;
    for (int it = 0; it < NIT; it++) {
        asm volatile("cp.async.wait_group 1;" ::: "memory");
        __syncthreads();
        if (it + 2 < NIT) {
            int ps = cur + 2; if (ps >= 3) ps -= 3;
            load_tile_g(sb + ps * GM_STAGE, tid, Ahi, Alo, Whi, Wlo,
                        bm, bn, K, (it + 2) * 32);
        }
        CP_COMMIT();

        const u32 bb = sb + cur * GM_STAGE;
        #pragma unroll
        for (int kk2 = 0; kk2 < 4; kk2 += 2) {
            u32 ah[4][4], al[4][4];
            #pragma unroll
            for (int i = 0; i < 4; i++) {
                u32 off = sw_off(wm + i * 16 + arow, kk2 + akh);
                ldsm4(ah[i], bb + off);
                ldsm4(al[i], bb + 16384 + off);
            }
            u32 wh4[4][4], wl4[4][4];
            #pragma unroll
            for (int jp = 0; jp < 4; jp++) {
                u32 off = sw_off(wn + (jp * 2 + bj) * 8 + brow, kk2 + bkc);
                ldsm4(wh4[jp], bb + 32768 + off);
                ldsm4(wl4[jp], bb + 40960 + off);
            }
            #pragma unroll
            for (int i = 0; i < 4; i++)
                #pragma unroll
                for (int j = 0; j < 8; j++) {
                    const u32* bh = &wh4[j >> 1][(j & 1) * 2];
                    const u32* bl = &wl4[j >> 1][(j & 1) * 2];
                    mma16816(acc[i][j], ah[i], bh);
                    mma16816(acc[i][j], ah[i], bl);
                    mma16816(acc[i][j], al[i], bh);
                }
        }
        cur = (cur == 2) ? 0 : cur + 1;
    }

    const int g = lane >> 2, tc = lane & 3;
    #pragma unroll
    for (int i = 0; i < 4; i++) {
        #pragma unroll
        for (int j = 0; j < 8; j++) {
            const int col = bn + wn + j * 8 + tc * 2;
            const size_t r0 = (size_t)(bm + wm + i * 16 + g) * N + col;
            const size_t r1 = r0 + (size_t)8 * N;
            if (Cf) {
                float b0 = bias ? bias[col] : 0.f;
                float b1 = bias ? bias[col + 1] : 0.f;
                *(float2*)&Cf[r0] = make_float2(acc[i][j][0] + b0, acc[i][j][1] + b1);
                *(float2*)&Cf[r1] = make_float2(acc[i][j][2] + b0, acc[i][j][3] + b1);
            } else {
                u32 hw, lw;
                split2(acc[i][j][0], acc[i][j][1], hw, lw);
                *(u32*)&Oh[r0] = hw; *(u32*)&Ol[r0] = lw;
                split2(acc[i][j][2], acc[i][j][3], hw, lw);
                *(u32*)&Oh[r1] = hw; *(u32*)&Ol[r1] = lw;
            }
        }
    }
}

// ---------------------------------------------------------------------------
// HMMA sp2norm attention (R6 winner: 2 KV buffers, 2 CTAs/SM).
// ---------------------------------------------------------------------------
#define AT_QH 0
#define AT_QL 16384
#define AT_BUF 32768
#define AT_SMEM_BYTES (32768 + 2 * 32768)

__device__ __forceinline__ void ldsm2(u32* r, u32 addr) {
    asm volatile("ldmatrix.sync.aligned.m8n8.x2.shared.b16 {%0,%1}, [%2];"
                 : "=r"(r[0]), "=r"(r[1]) : "r"(addr));
}

__device__ __forceinline__ void load_kv_a(
    u32 dst, int tid, const __nv_bfloat16* __restrict__ qhi,
    const __nv_bfloat16* __restrict__ qlo, size_t kvbase)
{
    #pragma unroll
    for (int q = 0; q < 2; q++) {
        int slot = tid + q * 256;
        int r = slot >> 3;
        int c = slot & 7;
        u32 so = (u32)(r * 128 + ((c ^ (r & 7)) << 4));
        size_t gk = kvbase + (size_t)r * (3 * CC) + CC + c * 8;
        size_t gv = gk + CC;
        cpa16(dst +         so, qhi + gk);
        cpa16(dst +  8192 + so, qlo + gk);
        cpa16(dst + 16384 + so, qhi + gv);
        cpa16(dst + 24576 + so, qlo + gv);
    }
}

__global__ __launch_bounds__(256, 2)
void attn_mma(const __nv_bfloat16* __restrict__ qhi, const __nv_bfloat16* __restrict__ qlo,
              __nv_bfloat16* __restrict__ ahi, __nv_bfloat16* __restrict__ alo) {
    extern __shared__ char smem[];
    const u32 sb = s2u(smem);
    const int tid = threadIdx.x;
    const int wid = tid >> 5, lane = tid & 31;
    const int g = lane >> 2, tc = lane & 3;
    const int qb = gridDim.x - 1 - blockIdx.x;
    const int h = blockIdx.y, b = blockIdx.z;

    const size_t qbase = ((size_t)(b * TT + qb * 128)) * (3 * CC) + h * 64;

    #pragma unroll
    for (int q = 0; q < 4; q++) {
        int slot = tid + q * 256;
        int r = slot >> 3;
        int c = slot & 7;
        u32 so = (u32)(r * 128 + ((c ^ (r & 7)) << 4));
        size_t gq = qbase + (size_t)r * (3 * CC) + c * 8;
        cpa16(sb + AT_QH + so, qhi + gq);
        cpa16(sb + AT_QL + so, qlo + gq);
    }
    load_kv_a(sb + AT_BUF, tid, qhi, qlo, ((size_t)(b * TT)) * (3 * CC) + h * 64);
    CP_COMMIT();
    load_kv_a(sb + AT_BUF + 32768, tid, qhi, qlo,
              ((size_t)(b * TT + 64)) * (3 * CC) + h * 64);
    CP_COMMIT();
    asm volatile("cp.async.wait_group 1;" ::: "memory");
    __syncthreads();

    u32 qh[4][4], ql[4][4];
    {
        const int row = 16 * wid + (lane & 15);
        const int ckb = lane >> 4;
        #pragma unroll
        for (int t = 0; t < 4; t++) {
            int ck = 2 * t + ckb;
            u32 off = (u32)(row * 128 + ((ck ^ (row & 7)) << 4));
            ldsm4(qh[t], sb + AT_QH + off);
            ldsm4(ql[t], sb + AT_QL + off);
        }
    }

    float o[8][4];
    #pragma unroll
    for (int v = 0; v < 8; v++)
        #pragma unroll
        for (int u = 0; u < 4; u++) o[v][u] = 0.f;
    float rsq0 = 0.f, rsq1 = 0.f;

    const int qg0 = qb * 128 + 16 * wid + g;
    const int jmax = 2 * qb + 1;

    for (int j = 0; j <= jmax; j++) {
        const u32 bb = sb + AT_BUF + (j & 1) * 32768;
        const bool dg = (j >= 2 * qb);
        const bool act = !(dg && (j * 64 > qb * 128 + 16 * wid + 15));

        if (act) {
            float s[8][4];
            #pragma unroll
            for (int v = 0; v < 8; v++)
                #pragma unroll
                for (int u = 0; u < 4; u++) s[v][u] = 0.f;

            const int rowK = (lane & 7) + ((lane >> 4) << 3);
            const int ckK  = (lane >> 3) & 1;
            #pragma unroll
            for (int t = 0; t < 4; t++) {
                #pragma unroll
                for (int u = 0; u < 4; u++) {
                    int rK = 16 * u + rowK;
                    int ck = 2 * t + ckK;
                    u32 off = (u32)(rK * 128 + ((ck ^ (rK & 7)) << 4));
                    u32 kh[4], kl[4];
                    ldsm4(kh, bb + off);
                    ldsm4(kl, bb + 8192 + off);
                    mma16816(s[2*u],   qh[t], kh);
                    mma16816(s[2*u],   ql[t], kh);
                    mma16816(s[2*u],   qh[t], kl);
                    mma16816(s[2*u+1], qh[t], kh + 2);
                    mma16816(s[2*u+1], ql[t], kh + 2);
                    mma16816(s[2*u+1], qh[t], kl + 2);
                }
            }

            const int rowVb = (lane & 7) + (((lane >> 3) & 1) << 3);
            const int cvb = lane >> 4;
            #pragma unroll
            for (int t = 0; t < 4; t++) {
                float w0 = softplus_f(s[2*t][0]   * 0.125f);
                float w1 = softplus_f(s[2*t][1]   * 0.125f);
                float w2 = softplus_f(s[2*t][2]   * 0.125f);
                float w3 = softplus_f(s[2*t][3]   * 0.125f);
                float w4 = softplus_f(s[2*t+1][0] * 0.125f);
                float w5 = softplus_f(s[2*t+1][1] * 0.125f);
                float w6 = softplus_f(s[2*t+1][2] * 0.125f);
                float w7 = softplus_f(s[2*t+1][3] * 0.125f);
                if (dg) {
                    int kg = j * 64 + 16 * t + 2 * tc;
                    int q0 = qg0, q1 = qg0 + 8;
                    if (kg     > q0) w0 = 0.f;
                    if (kg + 1 > q0) w1 = 0.f;
                    if (kg     > q1) w2 = 0.f;
                    if (kg + 1 > q1) w3 = 0.f;
                    if (kg + 8 > q0) w4 = 0.f;
                    if (kg + 9 > q0) w5 = 0.f;
                    if (kg + 8 > q1) w6 = 0.f;
                    if (kg + 9 > q1) w7 = 0.f;
                }
                rsq0 = fmaf(w0, w0, rsq0); rsq0 = fmaf(w1, w1, rsq0);
                rsq0 = fmaf(w4, w4, rsq0); rsq0 = fmaf(w5, w5, rsq0);
                rsq1 = fmaf(w2, w2, rsq1); rsq1 = fmaf(w3, w3, rsq1);
                rsq1 = fmaf(w6, w6, rsq1); rsq1 = fmaf(w7, w7, rsq1);

                u32 wh[4], wl[4];
                split2(w0, w1, wh[0], wl[0]);
                split2(w2, w3, wh[1], wl[1]);
                split2(w4, w5, wh[2], wl[2]);
                split2(w6, w7, wh[3], wl[3]);

                const int rV = 16 * t + rowVb;
                #pragma unroll
                for (int v = 0; v < 4; v++) {
                    int cv = 2 * v + cvb;
                    u32 off = (u32)(rV * 128 + ((cv ^ (rV & 7)) << 4));
                    u32 vh[4], vl[4];
                    ldsm4t(vh, bb + 16384 + off);
                    ldsm4t(vl, bb + 24576 + off);
                    mma16816(o[2*v],   wh, vh);
                    mma16816(o[2*v],   wl, vh);
                    mma16816(o[2*v],   wh, vl);
                    mma16816(o[2*v+1], wh, vh + 2);
                    mma16816(o[2*v+1], wl, vh + 2);
                    mma16816(o[2*v+1], wh, vl + 2);
                }
            }
        }

        __syncthreads();
        if (j + 2 <= jmax) {
            load_kv_a(sb + AT_BUF + (j & 1) * 32768, tid, qhi, qlo,
                      ((size_t)(b * TT + (j + 2) * 64)) * (3 * CC) + h * 64);
        }
        CP_COMMIT();
        asm volatile("cp.async.wait_group 1;" ::: "memory");
        __syncthreads();
    }

    rsq0 += __shfl_xor_sync(0xffffffffu, rsq0, 1);
    rsq0 += __shfl_xor_sync(0xffffffffu, rsq0, 2);
    rsq1 += __shfl_xor_sync(0xffffffffu, rsq1, 1);
    rsq1 += __shfl_xor_sync(0xffffffffu, rsq1, 2);
    const float inv0 = rsqrtf(rsq0);
    const float inv1 = rsqrtf(rsq1);

    const size_t obase = (size_t)(b * TT + qg0) * CC + h * 64 + 2 * tc;
    #pragma unroll
    for (int v = 0; v < 8; v++) {
        u32 hw, lw;
        split2(o[v][0] * inv0, o[v][1] * inv0, hw, lw);
        *(u32*)&ahi[obase + 8 * v] = hw;
        *(u32*)&alo[obase + 8 * v] = lw;
        split2(o[v][2] * inv1, o[v][3] * inv1, hw, lw);
        *(u32*)&ahi[obase + 8 * (size_t)CC + 8 * v] = hw;
        *(u32*)&alo[obase + 8 * (size_t)CC + 8 * v] = lw;
    }
}

// ---------------------------------------------------------------------------
extern "C" void kernel_launch(void* const* d_in, const int* in_sizes, int n_in,
                              void* d_out, int out_size) {
    const float* x     = (const float*)d_in[0];
    const float* Wqkv  = (const float*)d_in[1];
    const float* Wproj = (const float*)d_in[2];
    const float* bproj = (const float*)d_in[3];
    float* out = (float*)d_out;

    __nv_bfloat16 *xhi, *xlo, *wqhi, *wqlo, *wphi, *wplo, *qhi, *qlo, *ahi, *alo;
    cudaGetSymbolAddress((void**)&xhi, g_xhi);
    cudaGetSymbolAddress((void**)&xlo, g_xlo);
    cudaGetSymbolAddress((void**)&wqhi, g_wqhi);
    cudaGetSymbolAddress((void**)&wqlo, g_wqlo);
    cudaGetSymbolAddress((void**)&wphi, g_wphi);
    cudaGetSymbolAddress((void**)&wplo, g_wplo);
    cudaGetSymbolAddress((void**)&qhi, g_qhi);
    cudaGetSymbolAddress((void**)&qlo, g_qlo);
    cudaGetSymbolAddress((void**)&ahi, g_ahi);
    cudaGetSymbolAddress((void**)&alo, g_alo);

    cudaFuncSetAttribute(gemm_mma, cudaFuncAttributeMaxDynamicSharedMemorySize,
                         GM_SMEM_BYTES);
    cudaFuncSetAttribute(attn_mma, cudaFuncAttributeMaxDynamicSharedMemorySize,
                         AT_SMEM_BYTES);

    int n4x = BT * CC / 4;
    int n4q = 3 * CC * CC / 4;
    int n4p = CC * CC / 4;
    split_bf16<<<(n4x + 255) / 256, 256>>>((const float4*)x, (uint2*)xhi, (uint2*)xlo, n4x);
    split_bf16<<<(n4q + 255) / 256, 256>>>((const float4*)Wqkv, (uint2*)wqhi, (uint2*)wqlo, n4q);
    split_bf16<<<(n4p + 255) / 256, 256>>>((const float4*)Wproj, (uint2*)wphi, (uint2*)wplo, n4p);

    // 1) QKV = x @ Wqkv^T -> bf16 hi/lo directly
    gemm_mma<<<dim3((3 * CC) / 128, BT / 256), 256, GM_SMEM_BYTES>>>(
        xhi, xlo, wqhi, wqlo, nullptr, nullptr, qhi, qlo, 3 * CC, CC);

    // 2) attention (causal sp2norm) -> bf16 hi/lo directly
    attn_mma<<<dim3(TT / 128, HH, BB), 256, AT_SMEM_BYTES>>>(qhi, qlo, ahi, alo);

    // 3) out = att @ Wproj^T + b (fp32)
    gemm_mma<<<dim3(CC / 128, BT / 256), 256, GM_SMEM_BYTES>>>(
        ahi, alo, wphi, wplo, bproj, out, nullptr, nullptr, CC, CC);
}

// round 9
// speedup vs baseline: 1.0702x; 1.0533x over previous
#include <cuda_runtime.h>
#include <cuda_fp16.h>
#include <math.h>

#define BB 2
#define TT 2048
#define CC 1024
#define HH 16
#define BT (BB*TT)   // 4096

typedef unsigned int u32;
typedef unsigned long long u64;

// ---------------------------------------------------------------------------
// Scratch (__device__ globals; no allocations allowed)
// ---------------------------------------------------------------------------
__device__ __align__(256) __half g_xhi[(size_t)BT * CC];
__device__ __align__(256) __half g_xlo[(size_t)BT * CC];
__device__ __align__(256) __half g_wqhi[(size_t)3 * CC * CC];
__device__ __align__(256) __half g_wqlo[(size_t)3 * CC * CC];
__device__ __align__(256) __half g_wphi[(size_t)CC * CC];
__device__ __align__(256) __half g_wplo[(size_t)CC * CC];
__device__ __align__(256) __half g_qhi[(size_t)BT * 3 * CC];
__device__ __align__(256) __half g_qlo[(size_t)BT * 3 * CC];
__device__ __align__(256) __half g_ahi[(size_t)BT * CC];
__device__ __align__(256) __half g_alo[(size_t)BT * CC];

// ---------------------------------------------------------------------------
// PTX helpers
// ---------------------------------------------------------------------------
__device__ __forceinline__ u32 s2u(const void* p) {
    u32 a;
    asm("{ .reg .u64 t; cvta.to.shared.u64 t, %1; cvt.u32.u64 %0, t; }"
        : "=r"(a) : "l"(p));
    return a;
}
__device__ __forceinline__ void cpa16(u32 dst, const void* src) {
    asm volatile("cp.async.cg.shared.global [%0], [%1], 16;" :: "r"(dst), "l"(src));
}
#define CP_COMMIT() asm volatile("cp.async.commit_group;" ::: "memory")
#define CP_WAIT0()  asm volatile("cp.async.wait_group 0;" ::: "memory")
__device__ __forceinline__ void ldsm4(u32* r, u32 addr) {
    asm volatile("ldmatrix.sync.aligned.m8n8.x4.shared.b16 {%0,%1,%2,%3}, [%4];"
                 : "=r"(r[0]), "=r"(r[1]), "=r"(r[2]), "=r"(r[3]) : "r"(addr));
}
__device__ __forceinline__ void ldsm4t(u32* r, u32 addr) {
    asm volatile("ldmatrix.sync.aligned.m8n8.x4.trans.shared.b16 {%0,%1,%2,%3}, [%4];"
                 : "=r"(r[0]), "=r"(r[1]), "=r"(r[2]), "=r"(r[3]) : "r"(addr));
}
__device__ __forceinline__ void ldsm2(u32* r, u32 addr) {
    asm volatile("ldmatrix.sync.aligned.m8n8.x2.shared.b16 {%0,%1}, [%2];"
                 : "=r"(r[0]), "=r"(r[1]) : "r"(addr));
}
__device__ __forceinline__ void mma16816(float* d, const u32* a, const u32* b) {
    asm volatile(
        "mma.sync.aligned.m16n8k16.row.col.f32.f16.f16.f32 "
        "{%0,%1,%2,%3}, {%4,%5,%6,%7}, {%8,%9}, {%0,%1,%2,%3};"
        : "+f"(d[0]), "+f"(d[1]), "+f"(d[2]), "+f"(d[3])
        : "r"(a[0]), "r"(a[1]), "r"(a[2]), "r"(a[3]), "r"(b[0]), "r"(b[1]));
}
// pack two fp32 into fp16x2 (lo = a, hi = b)
__device__ __forceinline__ u32 pack2h(float a, float b) {
    u32 d;
    asm("cvt.rn.f16x2.f32 %0, %1, %2;" : "=r"(d) : "f"(b), "f"(a));
    return d;
}
// fp32 pair -> fp16 hi word + fp16 residual lo word
__device__ __forceinline__ void split2h(float a, float b, u32& hw, u32& lw) {
    asm("cvt.rn.f16x2.f32 %0, %1, %2;" : "=r"(hw) : "f"(b), "f"(a));
    __half2 hh = *reinterpret_cast<__half2*>(&hw);
    float2 f = __half22float2(hh);      // f.x = a_hi, f.y = b_hi
    float la = a - f.x, lb = b - f.y;
    asm("cvt.rn.f16x2.f32 %0, %1, %2;" : "=r"(lw) : "f"(lb), "f"(la));
}
// softplus: max(x,0) + ln(1+e^{-|x|}); ln via ln1.5 + deg-9 series in y=(2e-1)/3
__device__ __forceinline__ float softplus_f(float x) {
    float e = __expf(-fabsf(x));
    float y = fmaf(e, 0.6666666667f, -0.3333333333f);
    float q = 0.1111111111f;
    q = fmaf(q, y, -0.125f);
    q = fmaf(q, y, 0.1428571429f);
    q = fmaf(q, y, -0.1666666667f);
    q = fmaf(q, y, 0.2f);
    q = fmaf(q, y, -0.25f);
    q = fmaf(q, y, 0.3333333333f);
    q = fmaf(q, y, -0.5f);
    q = fmaf(q, y, 1.0f);
    return fmaxf(x, 0.f) + fmaf(q, y, 0.4054651081f);
}

// ---------------------------------------------------------------------------
// fp32 -> fp16 hi/lo split kernel
// ---------------------------------------------------------------------------
__global__ __launch_bounds__(256)
void split_f16(const float4* __restrict__ src, uint2* __restrict__ hi,
               uint2* __restrict__ lo, int n4) {
    int i = blockIdx.x * blockDim.x + threadIdx.x;
    if (i >= n4) return;
    float4 v = src[i];
    u32 h0, l0, h1, l1;
    split2h(v.x, v.y, h0, l0);
    split2h(v.z, v.w, h1, l1);
    hi[i] = make_uint2(h0, h1);
    lo[i] = make_uint2(l0, l1);
}

// ---------------------------------------------------------------------------
// HMMA GEMM: C[M,N] = (Ahi+Alo)[M,K] @ (Whi+Wlo)[N,K]^T  (fp16 3-term)
// 128x128x32 tile, 8 warps, double buffer, ONE sync/iter, 2 CTAs/SM.
// Term-major MMA order for accumulator ILP.
// ---------------------------------------------------------------------------
#define GM_STAGE 32768
#define GM_SMEM_BYTES (2 * GM_STAGE)

__device__ __forceinline__ u32 sw_off(int r, int c) {
    return (u32)(((r << 2) + (c ^ ((r >> 1) & 3))) << 4);
}

__device__ __forceinline__ void load_tile_g(
    u32 sbuf, int tid,
    const __half* __restrict__ Ah, const __half* __restrict__ Al,
    const __half* __restrict__ Wh, const __half* __restrict__ Wl,
    int bm, int bn, int K, int k0)
{
    #pragma unroll
    for (int q = 0; q < 2; q++) {
        int idx = tid + q * 256;
        int r = idx >> 2;
        int c = idx & 3;
        u32 so = sw_off(r, c);
        size_t ga = (size_t)(bm + r) * K + k0 + c * 8;
        size_t gw = (size_t)(bn + r) * K + k0 + c * 8;
        cpa16(sbuf +         so, Ah + ga);
        cpa16(sbuf +  8192 + so, Al + ga);
        cpa16(sbuf + 16384 + so, Wh + gw);
        cpa16(sbuf + 24576 + so, Wl + gw);
    }
    CP_COMMIT();
}

__global__ __launch_bounds__(256, 2)
void gemm_mma(const __half* __restrict__ Ahi, const __half* __restrict__ Alo,
              const __half* __restrict__ Whi, const __half* __restrict__ Wlo,
              const float* __restrict__ bias, float* __restrict__ Cf,
              __half* __restrict__ Oh, __half* __restrict__ Ol,
              int N, int K) {
    extern __shared__ char smem[];
    const u32 sb = s2u(smem);
    const int tid = threadIdx.x;
    const int wid = tid >> 5, lane = tid & 31;
    const int bm = blockIdx.y * 128, bn = blockIdx.x * 128;
    const int wm = (wid >> 2) * 64;
    const int wn = (wid & 3) * 32;

    float acc[4][4][4];
    #pragma unroll
    for (int i = 0; i < 4; i++)
        #pragma unroll
        for (int j = 0; j < 4; j++)
            #pragma unroll
            for (int u = 0; u < 4; u++) acc[i][j][u] = 0.f;

    const int NIT = K / 32;

    load_tile_g(sb, tid, Ahi, Alo, Whi, Wlo, bm, bn, K, 0);

    const int arow = lane & 15;
    const int akh  = lane >> 4;
    const int brow = lane & 7;
    const int bkh  = (lane >> 3) & 1;

    for (int it = 0; it < NIT; it++) {
        CP_WAIT0();
        __syncthreads();   // stage (it&1) ready AND all warps done with prev compute
        if (it + 1 < NIT) {
            load_tile_g(sb + ((it + 1) & 1) * GM_STAGE, tid,
                        Ahi, Alo, Whi, Wlo, bm, bn, K, (it + 1) * 32);
        }

        const u32 bb = sb + (it & 1) * GM_STAGE;
        #pragma unroll
        for (int kk2 = 0; kk2 < 4; kk2 += 2) {
            u32 ah[4][4], al[4][4];
            #pragma unroll
            for (int i = 0; i < 4; i++) {
                u32 off = sw_off(wm + i * 16 + arow, kk2 + akh);
                ldsm4(ah[i], bb + off);
                ldsm4(al[i], bb + 8192 + off);
            }
            u32 wh[4][2], wl[4][2];
            #pragma unroll
            for (int j = 0; j < 4; j++) {
                u32 off = sw_off(wn + j * 8 + brow, kk2 + bkh);
                ldsm2(wh[j], bb + 16384 + off);
                ldsm2(wl[j], bb + 24576 + off);
            }
            // term-major: long RAW distance on each accumulator
            #pragma unroll
            for (int i = 0; i < 4; i++)
                #pragma unroll
                for (int j = 0; j < 4; j++) mma16816(acc[i][j], ah[i], wh[j]);
            #pragma unroll
            for (int i = 0; i < 4; i++)
                #pragma unroll
                for (int j = 0; j < 4; j++) mma16816(acc[i][j], ah[i], wl[j]);
            #pragma unroll
            for (int i = 0; i < 4; i++)
                #pragma unroll
                for (int j = 0; j < 4; j++) mma16816(acc[i][j], al[i], wh[j]);
        }
    }

    const int g = lane >> 2, tc = lane & 3;
    #pragma unroll
    for (int i = 0; i < 4; i++) {
        #pragma unroll
        for (int j = 0; j < 4; j++) {
            const int col = bn + wn + j * 8 + tc * 2;
            const size_t r0 = (size_t)(bm + wm + i * 16 + g) * N + col;
            const size_t r1 = r0 + (size_t)8 * N;
            if (Cf) {
                float b0 = bias ? bias[col] : 0.f;
                float b1 = bias ? bias[col + 1] : 0.f;
                *(float2*)&Cf[r0] = make_float2(acc[i][j][0] + b0, acc[i][j][1] + b1);
                *(float2*)&Cf[r1] = make_float2(acc[i][j][2] + b0, acc[i][j][3] + b1);
            } else {
                u32 hw, lw;
                split2h(acc[i][j][0], acc[i][j][1], hw, lw);
                *(u32*)&Oh[r0] = hw; *(u32*)&Ol[r0] = lw;
                split2h(acc[i][j][2], acc[i][j][3], hw, lw);
                *(u32*)&Oh[r1] = hw; *(u32*)&Ol[r1] = lw;
            }
        }
    }
}

// ---------------------------------------------------------------------------
// HMMA sp2norm attention (fp16). S = QK^T 3-term; O = W·V 2-term
// (W fp16-rounded, V exact hi+lo). 2 KV buffers, ONE sync per block, 2 CTAs/SM.
// ---------------------------------------------------------------------------
#define AT_QH 0
#define AT_QL 16384
#define AT_BUF 32768
#define AT_SMEM_BYTES (32768 + 2 * 32768)

__device__ __forceinline__ void load_kv_a(
    u32 dst, int tid, const __half* __restrict__ qhi,
    const __half* __restrict__ qlo, size_t kvbase)
{
    #pragma unroll
    for (int q = 0; q < 2; q++) {
        int slot = tid + q * 256;
        int r = slot >> 3;
        int c = slot & 7;
        u32 so = (u32)(r * 128 + ((c ^ (r & 7)) << 4));
        size_t gk = kvbase + (size_t)r * (3 * CC) + CC + c * 8;
        size_t gv = gk + CC;
        cpa16(dst +         so, qhi + gk);
        cpa16(dst +  8192 + so, qlo + gk);
        cpa16(dst + 16384 + so, qhi + gv);
        cpa16(dst + 24576 + so, qlo + gv);
    }
    CP_COMMIT();
}

__global__ __launch_bounds__(256, 2)
void attn_mma(const __half* __restrict__ qhi, const __half* __restrict__ qlo,
              __half* __restrict__ ahi, __half* __restrict__ alo) {
    extern __shared__ char smem[];
    const u32 sb = s2u(smem);
    const int tid = threadIdx.x;
    const int wid = tid >> 5, lane = tid & 31;
    const int g = lane >> 2, tc = lane & 3;
    const int qb = gridDim.x - 1 - blockIdx.x;
    const int h = blockIdx.y, b = blockIdx.z;

    const size_t qbase = ((size_t)(b * TT + qb * 128)) * (3 * CC) + h * 64;

    // Q (hi+lo) and KV block 0, one commit group
    #pragma unroll
    for (int q = 0; q < 4; q++) {
        int slot = tid + q * 256;
        int r = slot >> 3;
        int c = slot & 7;
        u32 so = (u32)(r * 128 + ((c ^ (r & 7)) << 4));
        size_t gq = qbase + (size_t)r * (3 * CC) + c * 8;
        cpa16(sb + AT_QH + so, qhi + gq);
        cpa16(sb + AT_QL + so, qlo + gq);
    }
    load_kv_a(sb + AT_BUF, tid, qhi, qlo, ((size_t)(b * TT)) * (3 * CC) + h * 64);
    CP_WAIT0();
    __syncthreads();

    u32 qh[4][4], ql[4][4];
    {
        const int row = 16 * wid + (lane & 15);
        const int ckb = lane >> 4;
        #pragma unroll
        for (int t = 0; t < 4; t++) {
            int ck = 2 * t + ckb;
            u32 off = (u32)(row * 128 + ((ck ^ (row & 7)) << 4));
            ldsm4(qh[t], sb + AT_QH + off);
            ldsm4(ql[t], sb + AT_QL + off);
        }
    }

    float o[8][4];
    #pragma unroll
    for (int v = 0; v < 8; v++)
        #pragma unroll
        for (int u = 0; u < 4; u++) o[v][u] = 0.f;
    float rsq0 = 0.f, rsq1 = 0.f;

    const int qg0 = qb * 128 + 16 * wid + g;
    const int jmax = 2 * qb + 1;

    for (int j = 0; j <= jmax; j++) {
        // prefetch next KV into the buffer freed at the end of last iter
        if (j < jmax) {
            load_kv_a(sb + AT_BUF + ((j + 1) & 1) * 32768, tid, qhi, qlo,
                      ((size_t)(b * TT + (j + 1) * 64)) * (3 * CC) + h * 64);
        } else {
            CP_COMMIT();
        }

        const u32 bb = sb + AT_BUF + (j & 1) * 32768;
        const bool dg = (j >= 2 * qb);
        const bool act = !(dg && (j * 64 > qb * 128 + 16 * wid + 15));

        if (act) {
            float s[8][4];
            #pragma unroll
            for (int v = 0; v < 8; v++)
                #pragma unroll
                for (int u = 0; u < 4; u++) s[v][u] = 0.f;

            const int rowK = (lane & 7) + ((lane >> 4) << 3);
            const int ckK  = (lane >> 3) & 1;
            #pragma unroll
            for (int t = 0; t < 4; t++) {
                #pragma unroll
                for (int u = 0; u < 4; u++) {
                    int rK = 16 * u + rowK;
                    int ck = 2 * t + ckK;
                    u32 off = (u32)(rK * 128 + ((ck ^ (rK & 7)) << 4));
                    u32 kh[4], kl[4];
                    ldsm4(kh, bb + off);
                    ldsm4(kl, bb + 8192 + off);
                    // alternate accumulators to break RAW chains
                    mma16816(s[2*u],   qh[t], kh);
                    mma16816(s[2*u+1], qh[t], kh + 2);
                    mma16816(s[2*u],   ql[t], kh);
                    mma16816(s[2*u+1], ql[t], kh + 2);
                    mma16816(s[2*u],   qh[t], kl);
                    mma16816(s[2*u+1], qh[t], kl + 2);
                }
            }

            const int rowVb = (lane & 7) + (((lane >> 3) & 1) << 3);
            const int cvb = lane >> 4;
            #pragma unroll
            for (int t = 0; t < 4; t++) {
                float w0 = softplus_f(s[2*t][0]   * 0.125f);
                float w1 = softplus_f(s[2*t][1]   * 0.125f);
                float w2 = softplus_f(s[2*t][2]   * 0.125f);
                float w3 = softplus_f(s[2*t][3]   * 0.125f);
                float w4 = softplus_f(s[2*t+1][0] * 0.125f);
                float w5 = softplus_f(s[2*t+1][1] * 0.125f);
                float w6 = softplus_f(s[2*t+1][2] * 0.125f);
                float w7 = softplus_f(s[2*t+1][3] * 0.125f);
                if (dg) {
                    int kg = j * 64 + 16 * t + 2 * tc;
                    int q0 = qg0, q1 = qg0 + 8;
                    if (kg     > q0) w0 = 0.f;
                    if (kg + 1 > q0) w1 = 0.f;
                    if (kg     > q1) w2 = 0.f;
                    if (kg + 1 > q1) w3 = 0.f;
                    if (kg + 8 > q0) w4 = 0.f;
                    if (kg + 9 > q0) w5 = 0.f;
                    if (kg + 8 > q1) w6 = 0.f;
                    if (kg + 9 > q1) w7 = 0.f;
                }
                rsq0 = fmaf(w0, w0, rsq0); rsq0 = fmaf(w1, w1, rsq0);
                rsq0 = fmaf(w4, w4, rsq0); rsq0 = fmaf(w5, w5, rsq0);
                rsq1 = fmaf(w2, w2, rsq1); rsq1 = fmaf(w3, w3, rsq1);
                rsq1 = fmaf(w6, w6, rsq1); rsq1 = fmaf(w7, w7, rsq1);

                u32 wh[4];
                wh[0] = pack2h(w0, w1);
                wh[1] = pack2h(w2, w3);
                wh[2] = pack2h(w4, w5);
                wh[3] = pack2h(w6, w7);

                const int rV = 16 * t + rowVb;
                #pragma unroll
                for (int v = 0; v < 4; v++) {
                    int cv = 2 * v + cvb;
                    u32 off = (u32)(rV * 128 + ((cv ^ (rV & 7)) << 4));
                    u32 vh[4], vl[4];
                    ldsm4t(vh, bb + 16384 + off);
                    ldsm4t(vl, bb + 24576 + off);
                    mma16816(o[2*v],   wh, vh);
                    mma16816(o[2*v+1], wh, vh + 2);
                    mma16816(o[2*v],   wh, vl);
                    mma16816(o[2*v+1], wh, vl + 2);
                }
            }
        }

        CP_WAIT0();        // KV(j+1) landed
        __syncthreads();   // all warps done reading buf(j&1) -> free next iter
    }

    rsq0 += __shfl_xor_sync(0xffffffffu, rsq0, 1);
    rsq0 += __shfl_xor_sync(0xffffffffu, rsq0, 2);
    rsq1 += __shfl_xor_sync(0xffffffffu, rsq1, 1);
    rsq1 += __shfl_xor_sync(0xffffffffu, rsq1, 2);
    const float inv0 = rsqrtf(rsq0);
    const float inv1 = rsqrtf(rsq1);

    const size_t obase = (size_t)(b * TT + qg0) * CC + h * 64 + 2 * tc;
    #pragma unroll
    for (int v = 0; v < 8; v++) {
        u32 hw, lw;
        split2h(o[v][0] * inv0, o[v][1] * inv0, hw, lw);
        *(u32*)&ahi[obase + 8 * v] = hw;
        *(u32*)&alo[obase + 8 * v] = lw;
        split2h(o[v][2] * inv1, o[v][3] * inv1, hw, lw);
        *(u32*)&ahi[obase + 8 * (size_t)CC + 8 * v] = hw;
        *(u32*)&alo[obase + 8 * (size_t)CC + 8 * v] = lw;
    }
}

// ---------------------------------------------------------------------------
extern "C" void kernel_launch(void* const* d_in, const int* in_sizes, int n_in,
                              void* d_out, int out_size) {
    const float* x     = (const float*)d_in[0];
    const float* Wqkv  = (const float*)d_in[1];
    const float* Wproj = (const float*)d_in[2];
    const float* bproj = (const float*)d_in[3];
    float* out = (float*)d_out;

    __half *xhi, *xlo, *wqhi, *wqlo, *wphi, *wplo, *qhi, *qlo, *ahi, *alo;
    cudaGetSymbolAddress((void**)&xhi, g_xhi);
    cudaGetSymbolAddress((void**)&xlo, g_xlo);
    cudaGetSymbolAddress((void**)&wqhi, g_wqhi);
    cudaGetSymbolAddress((void**)&wqlo, g_wqlo);
    cudaGetSymbolAddress((void**)&wphi, g_wphi);
    cudaGetSymbolAddress((void**)&wplo, g_wplo);
    cudaGetSymbolAddress((void**)&qhi, g_qhi);
    cudaGetSymbolAddress((void**)&qlo, g_qlo);
    cudaGetSymbolAddress((void**)&ahi, g_ahi);
    cudaGetSymbolAddress((void**)&alo, g_alo);

    cudaFuncSetAttribute(gemm_mma, cudaFuncAttributeMaxDynamicSharedMemorySize,
                         GM_SMEM_BYTES);
    cudaFuncSetAttribute(attn_mma, cudaFuncAttributeMaxDynamicSharedMemorySize,
                         AT_SMEM_BYTES);

    int n4x = BT * CC / 4;
    int n4q = 3 * CC * CC / 4;
    int n4p = CC * CC / 4;
    split_f16<<<(n4x + 255) / 256, 256>>>((const float4*)x, (uint2*)xhi, (uint2*)xlo, n4x);
    split_f16<<<(n4q + 255) / 256, 256>>>((const float4*)Wqkv, (uint2*)wqhi, (uint2*)wqlo, n4q);
    split_f16<<<(n4p + 255) / 256, 256>>>((const float4*)Wproj, (uint2*)wphi, (uint2*)wplo, n4p);

    // 1) QKV = x @ Wqkv^T -> fp16 hi/lo directly
    gemm_mma<<<dim3((3 * CC) / 128, BT / 128), 256, GM_SMEM_BYTES>>>(
        xhi, xlo, wqhi, wqlo, nullptr, nullptr, qhi, qlo, 3 * CC, CC);

    // 2) attention (causal sp2norm) -> fp16 hi/lo directly
    attn_mma<<<dim3(TT / 128, HH, BB), 256, AT_SMEM_BYTES>>>(qhi, qlo, ahi, alo);

    // 3) out = att @ Wproj^T + b (fp32)
    gemm_mma<<<dim3(CC / 128, BT / 128), 256, GM_SMEM_BYTES>>>(
        ahi, alo, wphi, wplo, bproj, out, nullptr, nullptr, CC, CC);
}

// round 10
// speedup vs baseline: 1.4297x; 1.3358x over previous
#include <cuda_runtime.h>
#include <cuda_fp16.h>
#include <math.h>

#define BB 2
#define TT 2048
#define CC 1024
#define HH 16
#define BT (BB*TT)   // 4096

typedef unsigned int u32;
typedef unsigned long long u64;

// ---------------------------------------------------------------------------
// Scratch (__device__ globals; no allocations allowed)
// ---------------------------------------------------------------------------
__device__ __align__(256) __half g_xhi[(size_t)BT * CC];
__device__ __align__(256) __half g_xlo[(size_t)BT * CC];
__device__ __align__(256) __half g_wqhi[(size_t)3 * CC * CC];
__device__ __align__(256) __half g_wphi[(size_t)CC * CC];
__device__ __align__(256) __half g_qhi[(size_t)BT * 3 * CC];
__device__ __align__(256) __half g_qlo[(size_t)BT * 3 * CC];
__device__ __align__(256) __half g_ahi[(size_t)BT * CC];
__device__ __align__(256) __half g_alo[(size_t)BT * CC];

// ---------------------------------------------------------------------------
// PTX helpers
// ---------------------------------------------------------------------------
__device__ __forceinline__ u32 s2u(const void* p) {
    u32 a;
    asm("{ .reg .u64 t; cvta.to.shared.u64 t, %1; cvt.u32.u64 %0, t; }"
        : "=r"(a) : "l"(p));
    return a;
}
__device__ __forceinline__ void cpa16(u32 dst, const void* src) {
    asm volatile("cp.async.cg.shared.global [%0], [%1], 16;" :: "r"(dst), "l"(src));
}
#define CP_COMMIT() asm volatile("cp.async.commit_group;" ::: "memory")
#define CP_WAIT0()  asm volatile("cp.async.wait_group 0;" ::: "memory")
__device__ __forceinline__ void ldsm4(u32* r, u32 addr) {
    asm volatile("ldmatrix.sync.aligned.m8n8.x4.shared.b16 {%0,%1,%2,%3}, [%4];"
                 : "=r"(r[0]), "=r"(r[1]), "=r"(r[2]), "=r"(r[3]) : "r"(addr));
}
__device__ __forceinline__ void ldsm4t(u32* r, u32 addr) {
    asm volatile("ldmatrix.sync.aligned.m8n8.x4.trans.shared.b16 {%0,%1,%2,%3}, [%4];"
                 : "=r"(r[0]), "=r"(r[1]), "=r"(r[2]), "=r"(r[3]) : "r"(addr));
}
__device__ __forceinline__ void ldsm2(u32* r, u32 addr) {
    asm volatile("ldmatrix.sync.aligned.m8n8.x2.shared.b16 {%0,%1}, [%2];"
                 : "=r"(r[0]), "=r"(r[1]) : "r"(addr));
}
__device__ __forceinline__ void mma16816(float* d, const u32* a, const u32* b) {
    asm volatile(
        "mma.sync.aligned.m16n8k16.row.col.f32.f16.f16.f32 "
        "{%0,%1,%2,%3}, {%4,%5,%6,%7}, {%8,%9}, {%0,%1,%2,%3};"
        : "+f"(d[0]), "+f"(d[1]), "+f"(d[2]), "+f"(d[3])
        : "r"(a[0]), "r"(a[1]), "r"(a[2]), "r"(a[3]), "r"(b[0]), "r"(b[1]));
}
// pack two fp32 into fp16x2
__device__ __forceinline__ u32 pack2h(float a, float b) {
    u32 d;
    asm("cvt.rn.f16x2.f32 %0, %1, %2;" : "=r"(d) : "f"(b), "f"(a));
    return d;
}
// fp32 pair -> fp16 hi word + fp16 residual lo word
__device__ __forceinline__ void split2h(float a, float b, u32& hw, u32& lw) {
    asm("cvt.rn.f16x2.f32 %0, %1, %2;" : "=r"(hw) : "f"(b), "f"(a));
    __half2 hh = *reinterpret_cast<__half2*>(&hw);
    float2 f = __half22float2(hh);
    float la = a - f.x, lb = b - f.y;
    asm("cvt.rn.f16x2.f32 %0, %1, %2;" : "=r"(lw) : "f"(lb), "f"(la));
}
// softplus via fast exp + fast log (MUFU)
__device__ __forceinline__ float softplus_f(float x) {
    float e = __expf(-fabsf(x));
    return fmaxf(x, 0.f) + __logf(1.f + e);
}

// ---------------------------------------------------------------------------
// fp32 -> fp16 hi/lo split kernel; and hi-only rounding kernel for weights
// ---------------------------------------------------------------------------
__global__ __launch_bounds__(256)
void split_f16(const float4* __restrict__ src, uint2* __restrict__ hi,
               uint2* __restrict__ lo, int n4) {
    int i = blockIdx.x * blockDim.x + threadIdx.x;
    if (i >= n4) return;
    float4 v = src[i];
    u32 h0, l0, h1, l1;
    split2h(v.x, v.y, h0, l0);
    split2h(v.z, v.w, h1, l1);
    hi[i] = make_uint2(h0, h1);
    lo[i] = make_uint2(l0, l1);
}
__global__ __launch_bounds__(256)
void round_f16(const float4* __restrict__ src, uint2* __restrict__ hi, int n4) {
    int i = blockIdx.x * blockDim.x + threadIdx.x;
    if (i >= n4) return;
    float4 v = src[i];
    hi[i] = make_uint2(pack2h(v.x, v.y), pack2h(v.z, v.w));
}

// ---------------------------------------------------------------------------
// HMMA GEMM (2-term): C[M,N] = (Ahi+Alo)[M,K] @ Whi[N,K]^T
// 128x128x32 tile, 8 warps, double buffer, ONE sync/iter, 2 CTAs/SM.
// Stage (24KB): Ah[8K] Al[8K] Wh[8K].
// ---------------------------------------------------------------------------
#define GM_STAGE 24576
#define GM_SMEM_BYTES (2 * GM_STAGE)

__device__ __forceinline__ u32 sw_off(int r, int c) {
    return (u32)(((r << 2) + (c ^ ((r >> 1) & 3))) << 4);
}

__device__ __forceinline__ void load_tile_g(
    u32 sbuf, int tid,
    const __half* __restrict__ Ah, const __half* __restrict__ Al,
    const __half* __restrict__ Wh,
    int bm, int bn, int K, int k0)
{
    #pragma unroll
    for (int q = 0; q < 2; q++) {
        int idx = tid + q * 256;
        int r = idx >> 2;
        int c = idx & 3;
        u32 so = sw_off(r, c);
        size_t ga = (size_t)(bm + r) * K + k0 + c * 8;
        size_t gw = (size_t)(bn + r) * K + k0 + c * 8;
        cpa16(sbuf +         so, Ah + ga);
        cpa16(sbuf +  8192 + so, Al + ga);
        cpa16(sbuf + 16384 + so, Wh + gw);
    }
    CP_COMMIT();
}

__global__ __launch_bounds__(256, 2)
void gemm_mma(const __half* __restrict__ Ahi, const __half* __restrict__ Alo,
              const __half* __restrict__ Whi,
              const float* __restrict__ bias, float* __restrict__ Cf,
              __half* __restrict__ Oh, __half* __restrict__ Ol,
              int N, int K) {
    extern __shared__ char smem[];
    const u32 sb = s2u(smem);
    const int tid = threadIdx.x;
    const int wid = tid >> 5, lane = tid & 31;
    const int bm = blockIdx.y * 128, bn = blockIdx.x * 128;
    const int wm = (wid >> 2) * 64;
    const int wn = (wid & 3) * 32;

    float acc[4][4][4];
    #pragma unroll
    for (int i = 0; i < 4; i++)
        #pragma unroll
        for (int j = 0; j < 4; j++)
            #pragma unroll
            for (int u = 0; u < 4; u++) acc[i][j][u] = 0.f;

    const int NIT = K / 32;

    load_tile_g(sb, tid, Ahi, Alo, Whi, bm, bn, K, 0);

    const int arow = lane & 15;
    const int akh  = lane >> 4;
    const int brow = lane & 7;
    const int bkh  = (lane >> 3) & 1;

    for (int it = 0; it < NIT; it++) {
        CP_WAIT0();
        __syncthreads();
        if (it + 1 < NIT) {
            load_tile_g(sb + ((it + 1) & 1) * GM_STAGE, tid,
                        Ahi, Alo, Whi, bm, bn, K, (it + 1) * 32);
        }

        const u32 bb = sb + (it & 1) * GM_STAGE;
        #pragma unroll
        for (int kk2 = 0; kk2 < 4; kk2 += 2) {
            u32 ah[4][4], al[4][4];
            #pragma unroll
            for (int i = 0; i < 4; i++) {
                u32 off = sw_off(wm + i * 16 + arow, kk2 + akh);
                ldsm4(ah[i], bb + off);
                ldsm4(al[i], bb + 8192 + off);
            }
            u32 wh[4][2];
            #pragma unroll
            for (int j = 0; j < 4; j++) {
                u32 off = sw_off(wn + j * 8 + brow, kk2 + bkh);
                ldsm2(wh[j], bb + 16384 + off);
            }
            // term-major for accumulator ILP
            #pragma unroll
            for (int i = 0; i < 4; i++)
                #pragma unroll
                for (int j = 0; j < 4; j++) mma16816(acc[i][j], ah[i], wh[j]);
            #pragma unroll
            for (int i = 0; i < 4; i++)
                #pragma unroll
                for (int j = 0; j < 4; j++) mma16816(acc[i][j], al[i], wh[j]);
        }
    }

    const int g = lane >> 2, tc = lane & 3;
    #pragma unroll
    for (int i = 0; i < 4; i++) {
        #pragma unroll
        for (int j = 0; j < 4; j++) {
            const int col = bn + wn + j * 8 + tc * 2;
            const size_t r0 = (size_t)(bm + wm + i * 16 + g) * N + col;
            const size_t r1 = r0 + (size_t)8 * N;
            if (Cf) {
                float b0 = bias ? bias[col] : 0.f;
                float b1 = bias ? bias[col + 1] : 0.f;
                *(float2*)&Cf[r0] = make_float2(acc[i][j][0] + b0, acc[i][j][1] + b1);
                *(float2*)&Cf[r1] = make_float2(acc[i][j][2] + b0, acc[i][j][3] + b1);
            } else {
                u32 hw, lw;
                split2h(acc[i][j][0], acc[i][j][1], hw, lw);
                *(u32*)&Oh[r0] = hw; *(u32*)&Ol[r0] = lw;
                split2h(acc[i][j][2], acc[i][j][3], hw, lw);
                *(u32*)&Oh[r1] = hw; *(u32*)&Ol[r1] = lw;
            }
        }
    }
}

// ---------------------------------------------------------------------------
// HMMA sp2norm attention (fp16). S = (Qh+Ql)·Kh (2-term, K rounded);
// O = Wh·(Vh+Vl) (2-term, W rounded). 2 KV buffers, ONE sync/block, 2 CTAs/SM.
// KV stage (24KB): Kh[8K] Vh[8K] Vl[8K]. Q region 32KB (Qh+Ql).
// ---------------------------------------------------------------------------
#define AT_QH 0
#define AT_QL 16384
#define AT_BUF 32768
#define AT_STAGE 24576
#define AT_SMEM_BYTES (32768 + 2 * AT_STAGE)

__device__ __forceinline__ void load_kv_a(
    u32 dst, int tid, const __half* __restrict__ qhi,
    const __half* __restrict__ qlo, size_t kvbase)
{
    #pragma unroll
    for (int q = 0; q < 2; q++) {
        int slot = tid + q * 256;
        int r = slot >> 3;
        int c = slot & 7;
        u32 so = (u32)(r * 128 + ((c ^ (r & 7)) << 4));
        size_t gk = kvbase + (size_t)r * (3 * CC) + CC + c * 8;
        size_t gv = gk + CC;
        cpa16(dst +         so, qhi + gk);   // K hi only
        cpa16(dst +  8192 + so, qhi + gv);   // V hi
        cpa16(dst + 16384 + so, qlo + gv);   // V lo
    }
    CP_COMMIT();
}

__global__ __launch_bounds__(256, 2)
void attn_mma(const __half* __restrict__ qhi, const __half* __restrict__ qlo,
              __half* __restrict__ ahi, __half* __restrict__ alo) {
    extern __shared__ char smem[];
    const u32 sb = s2u(smem);
    const int tid = threadIdx.x;
    const int wid = tid >> 5, lane = tid & 31;
    const int g = lane >> 2, tc = lane & 3;
    const int qb = gridDim.x - 1 - blockIdx.x;
    const int h = blockIdx.y, b = blockIdx.z;

    const size_t qbase = ((size_t)(b * TT + qb * 128)) * (3 * CC) + h * 64;

    #pragma unroll
    for (int q = 0; q < 4; q++) {
        int slot = tid + q * 256;
        int r = slot >> 3;
        int c = slot & 7;
        u32 so = (u32)(r * 128 + ((c ^ (r & 7)) << 4));
        size_t gq = qbase + (size_t)r * (3 * CC) + c * 8;
        cpa16(sb + AT_QH + so, qhi + gq);
        cpa16(sb + AT_QL + so, qlo + gq);
    }
    load_kv_a(sb + AT_BUF, tid, qhi, qlo, ((size_t)(b * TT)) * (3 * CC) + h * 64);
    CP_WAIT0();
    __syncthreads();

    u32 qh[4][4], ql[4][4];
    {
        const int row = 16 * wid + (lane & 15);
        const int ckb = lane >> 4;
        #pragma unroll
        for (int t = 0; t < 4; t++) {
            int ck = 2 * t + ckb;
            u32 off = (u32)(row * 128 + ((ck ^ (row & 7)) << 4));
            ldsm4(qh[t], sb + AT_QH + off);
            ldsm4(ql[t], sb + AT_QL + off);
        }
    }

    float o[8][4];
    #pragma unroll
    for (int v = 0; v < 8; v++)
        #pragma unroll
        for (int u = 0; u < 4; u++) o[v][u] = 0.f;
    float rsq0 = 0.f, rsq1 = 0.f;

    const int qg0 = qb * 128 + 16 * wid + g;
    const int jmax = 2 * qb + 1;

    for (int j = 0; j <= jmax; j++) {
        if (j < jmax) {
            load_kv_a(sb + AT_BUF + ((j + 1) & 1) * AT_STAGE, tid, qhi, qlo,
                      ((size_t)(b * TT + (j + 1) * 64)) * (3 * CC) + h * 64);
        } else {
            CP_COMMIT();
        }

        const u32 bb = sb + AT_BUF + (j & 1) * AT_STAGE;
        const bool dg = (j >= 2 * qb);
        const bool act = !(dg && (j * 64 > qb * 128 + 16 * wid + 15));

        if (act) {
            float s[8][4];
            #pragma unroll
            for (int v = 0; v < 8; v++)
                #pragma unroll
                for (int u = 0; u < 4; u++) s[v][u] = 0.f;

            const int rowK = (lane & 7) + ((lane >> 4) << 3);
            const int ckK  = (lane >> 3) & 1;
            #pragma unroll
            for (int t = 0; t < 4; t++) {
                #pragma unroll
                for (int u = 0; u < 4; u++) {
                    int rK = 16 * u + rowK;
                    int ck = 2 * t + ckK;
                    u32 off = (u32)(rK * 128 + ((ck ^ (rK & 7)) << 4));
                    u32 kh[4];
                    ldsm4(kh, bb + off);
                    mma16816(s[2*u],   qh[t], kh);
                    mma16816(s[2*u+1], qh[t], kh + 2);
                    mma16816(s[2*u],   ql[t], kh);
                    mma16816(s[2*u+1], ql[t], kh + 2);
                }
            }

            const int rowVb = (lane & 7) + (((lane >> 3) & 1) << 3);
            const int cvb = lane >> 4;
            #pragma unroll
            for (int t = 0; t < 4; t++) {
                float w0 = softplus_f(s[2*t][0]   * 0.125f);
                float w1 = softplus_f(s[2*t][1]   * 0.125f);
                float w2 = softplus_f(s[2*t][2]   * 0.125f);
                float w3 = softplus_f(s[2*t][3]   * 0.125f);
                float w4 = softplus_f(s[2*t+1][0] * 0.125f);
                float w5 = softplus_f(s[2*t+1][1] * 0.125f);
                float w6 = softplus_f(s[2*t+1][2] * 0.125f);
                float w7 = softplus_f(s[2*t+1][3] * 0.125f);
                if (dg) {
                    int kg = j * 64 + 16 * t + 2 * tc;
                    int q0 = qg0, q1 = qg0 + 8;
                    if (kg     > q0) w0 = 0.f;
                    if (kg + 1 > q0) w1 = 0.f;
                    if (kg     > q1) w2 = 0.f;
                    if (kg + 1 > q1) w3 = 0.f;
                    if (kg + 8 > q0) w4 = 0.f;
                    if (kg + 9 > q0) w5 = 0.f;
                    if (kg + 8 > q1) w6 = 0.f;
                    if (kg + 9 > q1) w7 = 0.f;
                }
                rsq0 = fmaf(w0, w0, rsq0); rsq0 = fmaf(w1, w1, rsq0);
                rsq0 = fmaf(w4, w4, rsq0); rsq0 = fmaf(w5, w5, rsq0);
                rsq1 = fmaf(w2, w2, rsq1); rsq1 = fmaf(w3, w3, rsq1);
                rsq1 = fmaf(w6, w6, rsq1); rsq1 = fmaf(w7, w7, rsq1);

                u32 wh[4];
                wh[0] = pack2h(w0, w1);
                wh[1] = pack2h(w2, w3);
                wh[2] = pack2h(w4, w5);
                wh[3] = pack2h(w6, w7);

                const int rV = 16 * t + rowVb;
                #pragma unroll
                for (int v = 0; v < 4; v++) {
                    int cv = 2 * v + cvb;
                    u32 off = (u32)(rV * 128 + ((cv ^ (rV & 7)) << 4));
                    u32 vh[4], vl[4];
                    ldsm4t(vh, bb +  8192 + off);
                    ldsm4t(vl, bb + 16384 + off);
                    mma16816(o[2*v],   wh, vh);
                    mma16816(o[2*v+1], wh, vh + 2);
                    mma16816(o[2*v],   wh, vl);
                    mma16816(o[2*v+1], wh, vl + 2);
                }
            }
        }

        CP_WAIT0();
        __syncthreads();
    }

    rsq0 += __shfl_xor_sync(0xffffffffu, rsq0, 1);
    rsq0 += __shfl_xor_sync(0xffffffffu, rsq0, 2);
    rsq1 += __shfl_xor_sync(0xffffffffu, rsq1, 1);
    rsq1 += __shfl_xor_sync(0xffffffffu, rsq1, 2);
    const float inv0 = rsqrtf(rsq0);
    const float inv1 = rsqrtf(rsq1);

    const size_t obase = (size_t)(b * TT + qg0) * CC + h * 64 + 2 * tc;
    #pragma unroll
    for (int v = 0; v < 8; v++) {
        u32 hw, lw;
        split2h(o[v][0] * inv0, o[v][1] * inv0, hw, lw);
        *(u32*)&ahi[obase + 8 * v] = hw;
        *(u32*)&alo[obase + 8 * v] = lw;
        split2h(o[v][2] * inv1, o[v][3] * inv1, hw, lw);
        *(u32*)&ahi[obase + 8 * (size_t)CC + 8 * v] = hw;
        *(u32*)&alo[obase + 8 * (size_t)CC + 8 * v] = lw;
    }
}

// ---------------------------------------------------------------------------
extern "C" void kernel_launch(void* const* d_in, const int* in_sizes, int n_in,
                              void* d_out, int out_size) {
    const float* x     = (const float*)d_in[0];
    const float* Wqkv  = (const float*)d_in[1];
    const float* Wproj = (const float*)d_in[2];
    const float* bproj = (const float*)d_in[3];
    float* out = (float*)d_out;

    __half *xhi, *xlo, *wqhi, *wphi, *qhi, *qlo, *ahi, *alo;
    cudaGetSymbolAddress((void**)&xhi, g_xhi);
    cudaGetSymbolAddress((void**)&xlo, g_xlo);
    cudaGetSymbolAddress((void**)&wqhi, g_wqhi);
    cudaGetSymbolAddress((void**)&wphi, g_wphi);
    cudaGetSymbolAddress((void**)&qhi, g_qhi);
    cudaGetSymbolAddress((void**)&qlo, g_qlo);
    cudaGetSymbolAddress((void**)&ahi, g_ahi);
    cudaGetSymbolAddress((void**)&alo, g_alo);

    cudaFuncSetAttribute(gemm_mma, cudaFuncAttributeMaxDynamicSharedMemorySize,
                         GM_SMEM_BYTES);
    cudaFuncSetAttribute(attn_mma, cudaFuncAttributeMaxDynamicSharedMemorySize,
                         AT_SMEM_BYTES);

    int n4x = BT * CC / 4;
    int n4q = 3 * CC * CC / 4;
    int n4p = CC * CC / 4;
    split_f16<<<(n4x + 255) / 256, 256>>>((const float4*)x, (uint2*)xhi, (uint2*)xlo, n4x);
    round_f16<<<(n4q + 255) / 256, 256>>>((const float4*)Wqkv, (uint2*)wqhi, n4q);
    round_f16<<<(n4p + 255) / 256, 256>>>((const float4*)Wproj, (uint2*)wphi, n4p);

    // 1) QKV = x @ Wqkv^T -> fp16 hi/lo directly
    gemm_mma<<<dim3((3 * CC) / 128, BT / 128), 256, GM_SMEM_BYTES>>>(
        xhi, xlo, wqhi, nullptr, nullptr, qhi, qlo, 3 * CC, CC);

    // 2) attention (causal sp2norm) -> fp16 hi/lo directly
    attn_mma<<<dim3(TT / 128, HH, BB), 256, AT_SMEM_BYTES>>>(qhi, qlo, ahi, alo);

    // 3) out = att @ Wproj^T + b (fp32)
    gemm_mma<<<dim3(CC / 128, BT / 128), 256, GM_SMEM_BYTES>>>(
        ahi, alo, wphi, bproj, out, nullptr, nullptr, CC, CC);
}

// round 11
// speedup vs baseline: 2.5628x; 1.7926x over previous
#include <cuda_runtime.h>
#include <cuda_fp16.h>
#include <math.h>

#define BB 2
#define TT 2048
#define CC 1024
#define HH 16
#define BT (BB*TT)   // 4096

typedef unsigned int u32;
typedef unsigned long long u64;

// ---------------------------------------------------------------------------
// Scratch (__device__ globals; no allocations allowed)
// ---------------------------------------------------------------------------
__device__ __align__(256) __half g_x[(size_t)BT * CC];
__device__ __align__(256) __half g_wq[(size_t)3 * CC * CC];
__device__ __align__(256) __half g_wp[(size_t)CC * CC];
__device__ __align__(256) __half g_qkv[(size_t)BT * 3 * CC];
__device__ __align__(256) __half g_att[(size_t)BT * CC];

// ---------------------------------------------------------------------------
// PTX helpers
// ---------------------------------------------------------------------------
__device__ __forceinline__ u32 s2u(const void* p) {
    u32 a;
    asm("{ .reg .u64 t; cvta.to.shared.u64 t, %1; cvt.u32.u64 %0, t; }"
        : "=r"(a) : "l"(p));
    return a;
}
__device__ __forceinline__ void cpa16(u32 dst, const void* src) {
    asm volatile("cp.async.cg.shared.global [%0], [%1], 16;" :: "r"(dst), "l"(src));
}
#define CP_COMMIT() asm volatile("cp.async.commit_group;" ::: "memory")
#define CP_WAIT0()  asm volatile("cp.async.wait_group 0;" ::: "memory")
__device__ __forceinline__ void ldsm4(u32* r, u32 addr) {
    asm volatile("ldmatrix.sync.aligned.m8n8.x4.shared.b16 {%0,%1,%2,%3}, [%4];"
                 : "=r"(r[0]), "=r"(r[1]), "=r"(r[2]), "=r"(r[3]) : "r"(addr));
}
__device__ __forceinline__ void ldsm4t(u32* r, u32 addr) {
    asm volatile("ldmatrix.sync.aligned.m8n8.x4.trans.shared.b16 {%0,%1,%2,%3}, [%4];"
                 : "=r"(r[0]), "=r"(r[1]), "=r"(r[2]), "=r"(r[3]) : "r"(addr));
}
__device__ __forceinline__ void mma16816(float* d, const u32* a, const u32* b) {
    asm volatile(
        "mma.sync.aligned.m16n8k16.row.col.f32.f16.f16.f32 "
        "{%0,%1,%2,%3}, {%4,%5,%6,%7}, {%8,%9}, {%0,%1,%2,%3};"
        : "+f"(d[0]), "+f"(d[1]), "+f"(d[2]), "+f"(d[3])
        : "r"(a[0]), "r"(a[1]), "r"(a[2]), "r"(a[3]), "r"(b[0]), "r"(b[1]));
}
__device__ __forceinline__ u32 pack2h(float a, float b) {
    u32 d;
    asm("cvt.rn.f16x2.f32 %0, %1, %2;" : "=r"(d) : "f"(b), "f"(a));
    return d;
}
// softplus via fast exp + fast log (MUFU)
__device__ __forceinline__ float softplus_f(float x) {
    float e = __expf(-fabsf(x));
    return fmaxf(x, 0.f) + __logf(1.f + e);
}

// ---------------------------------------------------------------------------
// fp32 -> fp16 rounding kernel
// ---------------------------------------------------------------------------
__global__ __launch_bounds__(256)
void round_f16(const float4* __restrict__ src, uint2* __restrict__ dst, int n4) {
    int i = blockIdx.x * blockDim.x + threadIdx.x;
    if (i >= n4) return;
    float4 v = src[i];
    dst[i] = make_uint2(pack2h(v.x, v.y), pack2h(v.z, v.w));
}

// ---------------------------------------------------------------------------
// HMMA GEMM (fp16 1-term): C[M,N] = A[M,K] @ W[N,K]^T
// 128x128x64 tile, 8 warps (2m x 4n), warp tile 64x32, double buffer,
// ONE sync per iter, 2 CTAs/SM. Stage (32KB): A[16K] W[16K], 128B rows,
// swizzle chunk' = c ^ (r&7).
// ---------------------------------------------------------------------------
#define GM_STAGE 32768
#define GM_SMEM_BYTES (2 * GM_STAGE)

__device__ __forceinline__ u32 sw8(int r, int c) {
    return (u32)(r * 128 + ((c ^ (r & 7)) << 4));
}

__device__ __forceinline__ void load_tile_g(
    u32 sbuf, int tid,
    const __half* __restrict__ A, const __half* __restrict__ W,
    int bm, int bn, int K, int k0)
{
    #pragma unroll
    for (int q = 0; q < 4; q++) {
        int idx = tid + q * 256;      // 0..1023
        int r = idx >> 3;             // 0..127
        int c = idx & 7;              // 0..7 (16B chunks)
        u32 so = sw8(r, c);
        cpa16(sbuf +         so, A + (size_t)(bm + r) * K + k0 + c * 8);
        cpa16(sbuf + 16384 + so, W + (size_t)(bn + r) * K + k0 + c * 8);
    }
    CP_COMMIT();
}

__global__ __launch_bounds__(256, 2)
void gemm_mma(const __half* __restrict__ A, const __half* __restrict__ W,
              const float* __restrict__ bias, float* __restrict__ Cf,
              __half* __restrict__ Oh, int N, int K) {
    extern __shared__ char smem[];
    const u32 sb = s2u(smem);
    const int tid = threadIdx.x;
    const int wid = tid >> 5, lane = tid & 31;
    const int bm = blockIdx.y * 128, bn = blockIdx.x * 128;
    const int wm = (wid >> 2) * 64;
    const int wn = (wid & 3) * 32;

    float acc[4][4][4];
    #pragma unroll
    for (int i = 0; i < 4; i++)
        #pragma unroll
        for (int j = 0; j < 4; j++)
            #pragma unroll
            for (int u = 0; u < 4; u++) acc[i][j][u] = 0.f;

    const int NIT = K / 64;   // 16

    load_tile_g(sb, tid, A, W, bm, bn, K, 0);

    const int arow = lane & 15;
    const int akh  = lane >> 4;
    const int bj   = (lane >> 4) & 1;    // n-frag within pair
    const int bkc  = (lane >> 3) & 1;    // k-chunk half
    const int brow = lane & 7;

    for (int it = 0; it < NIT; it++) {
        CP_WAIT0();
        __syncthreads();
        if (it + 1 < NIT) {
            load_tile_g(sb + ((it + 1) & 1) * GM_STAGE, tid,
                        A, W, bm, bn, K, (it + 1) * 64);
        }

        const u32 bb = sb + (it & 1) * GM_STAGE;
        #pragma unroll
        for (int kk2 = 0; kk2 < 8; kk2 += 2) {
            u32 ah[4][4];
            #pragma unroll
            for (int i = 0; i < 4; i++) {
                int row = wm + i * 16 + arow;
                ldsm4(ah[i], bb + sw8(row, kk2 + akh));
            }
            u32 wh4[2][4];
            #pragma unroll
            for (int jp = 0; jp < 2; jp++) {
                int row = wn + (jp * 2 + bj) * 8 + brow;
                ldsm4(wh4[jp], bb + 16384 + sw8(row, kk2 + bkc));
            }
            #pragma unroll
            for (int i = 0; i < 4; i++)
                #pragma unroll
                for (int j = 0; j < 4; j++)
                    mma16816(acc[i][j], ah[i], &wh4[j >> 1][(j & 1) * 2]);
        }
    }

    const int g = lane >> 2, tc = lane & 3;
    #pragma unroll
    for (int i = 0; i < 4; i++) {
        #pragma unroll
        for (int j = 0; j < 4; j++) {
            const int col = bn + wn + j * 8 + tc * 2;
            const size_t r0 = (size_t)(bm + wm + i * 16 + g) * N + col;
            const size_t r1 = r0 + (size_t)8 * N;
            if (Cf) {
                float b0 = bias ? bias[col] : 0.f;
                float b1 = bias ? bias[col + 1] : 0.f;
                *(float2*)&Cf[r0] = make_float2(acc[i][j][0] + b0, acc[i][j][1] + b1);
                *(float2*)&Cf[r1] = make_float2(acc[i][j][2] + b0, acc[i][j][3] + b1);
            } else {
                *(u32*)&Oh[r0] = pack2h(acc[i][j][0], acc[i][j][1]);
                *(u32*)&Oh[r1] = pack2h(acc[i][j][2], acc[i][j][3]);
            }
        }
    }
}

// ---------------------------------------------------------------------------
// HMMA sp2norm attention (fp16, 1-term S and WV).
// 128 q-rows x 8 warps; 2 KV buffers (16KB each: K[8K] V[8K]),
// ONE sync per block, 2 CTAs/SM. Q region 16KB.
// ---------------------------------------------------------------------------
#define AT_Q 0
#define AT_BUF 16384
#define AT_STAGE 16384
#define AT_SMEM_BYTES (16384 + 2 * AT_STAGE)

__device__ __forceinline__ void load_kv_a(
    u32 dst, int tid, const __half* __restrict__ qkv, size_t kvbase)
{
    #pragma unroll
    for (int q = 0; q < 2; q++) {
        int slot = tid + q * 256;     // 0..511
        int r = slot >> 3;            // 0..63
        int c = slot & 7;
        u32 so = sw8(r, c);
        size_t gk = kvbase + (size_t)r * (3 * CC) + CC + c * 8;
        cpa16(dst +        so, qkv + gk);        // K
        cpa16(dst + 8192 + so, qkv + gk + CC);   // V
    }
    CP_COMMIT();
}

__global__ __launch_bounds__(256, 2)
void attn_mma(const __half* __restrict__ qkv, __half* __restrict__ att) {
    extern __shared__ char smem[];
    const u32 sb = s2u(smem);
    const int tid = threadIdx.x;
    const int wid = tid >> 5, lane = tid & 31;
    const int g = lane >> 2, tc = lane & 3;
    const int qb = gridDim.x - 1 - blockIdx.x;
    const int h = blockIdx.y, b = blockIdx.z;

    const size_t qbase = ((size_t)(b * TT + qb * 128)) * (3 * CC) + h * 64;

    // Q tile 128x64 fp16 = 16KB and KV block 0, one commit group
    #pragma unroll
    for (int q = 0; q < 4; q++) {
        int slot = tid + q * 256;     // 0..1023
        int r = slot >> 3;            // 0..127
        int c = slot & 7;
        cpa16(sb + AT_Q + sw8(r, c), qkv + qbase + (size_t)r * (3 * CC) + c * 8);
    }
    load_kv_a(sb + AT_BUF, tid, qkv, ((size_t)(b * TT)) * (3 * CC) + h * 64);
    CP_WAIT0();
    __syncthreads();

    u32 qh[4][4];
    {
        const int row = 16 * wid + (lane & 15);
        const int ckb = lane >> 4;
        #pragma unroll
        for (int t = 0; t < 4; t++)
            ldsm4(qh[t], sb + AT_Q + sw8(row, 2 * t + ckb));
    }

    float o[8][4];
    #pragma unroll
    for (int v = 0; v < 8; v++)
        #pragma unroll
        for (int u = 0; u < 4; u++) o[v][u] = 0.f;
    float rsq0 = 0.f, rsq1 = 0.f;

    const int qg0 = qb * 128 + 16 * wid + g;
    const int jmax = 2 * qb + 1;

    for (int j = 0; j <= jmax; j++) {
        if (j < jmax) {
            load_kv_a(sb + AT_BUF + ((j + 1) & 1) * AT_STAGE, tid, qkv,
                      ((size_t)(b * TT + (j + 1) * 64)) * (3 * CC) + h * 64);
        } else {
            CP_COMMIT();
        }

        const u32 bb = sb + AT_BUF + (j & 1) * AT_STAGE;
        const bool dg = (j >= 2 * qb);
        const bool act = !(dg && (j * 64 > qb * 128 + 16 * wid + 15));

        if (act) {
            float s[8][4];
            #pragma unroll
            for (int v = 0; v < 8; v++)
                #pragma unroll
                for (int u = 0; u < 4; u++) s[v][u] = 0.f;

            const int rowK = (lane & 7) + ((lane >> 4) << 3);
            const int ckK  = (lane >> 3) & 1;
            #pragma unroll
            for (int t = 0; t < 4; t++) {
                #pragma unroll
                for (int u = 0; u < 4; u++) {
                    int rK = 16 * u + rowK;
                    u32 kh[4];
                    ldsm4(kh, bb + sw8(rK, 2 * t + ckK));
                    mma16816(s[2*u],   qh[t], kh);
                    mma16816(s[2*u+1], qh[t], kh + 2);
                }
            }

            const int rowVb = (lane & 7) + (((lane >> 3) & 1) << 3);
            const int cvb = lane >> 4;
            #pragma unroll
            for (int t = 0; t < 4; t++) {
                float w0 = softplus_f(s[2*t][0]   * 0.125f);
                float w1 = softplus_f(s[2*t][1]   * 0.125f);
                float w2 = softplus_f(s[2*t][2]   * 0.125f);
                float w3 = softplus_f(s[2*t][3]   * 0.125f);
                float w4 = softplus_f(s[2*t+1][0] * 0.125f);
                float w5 = softplus_f(s[2*t+1][1] * 0.125f);
                float w6 = softplus_f(s[2*t+1][2] * 0.125f);
                float w7 = softplus_f(s[2*t+1][3] * 0.125f);
                if (dg) {
                    int kg = j * 64 + 16 * t + 2 * tc;
                    int q0 = qg0, q1 = qg0 + 8;
                    if (kg     > q0) w0 = 0.f;
                    if (kg + 1 > q0) w1 = 0.f;
                    if (kg     > q1) w2 = 0.f;
                    if (kg + 1 > q1) w3 = 0.f;
                    if (kg + 8 > q0) w4 = 0.f;
                    if (kg + 9 > q0) w5 = 0.f;
                    if (kg + 8 > q1) w6 = 0.f;
                    if (kg + 9 > q1) w7 = 0.f;
                }
                rsq0 = fmaf(w0, w0, rsq0); rsq0 = fmaf(w1, w1, rsq0);
                rsq0 = fmaf(w4, w4, rsq0); rsq0 = fmaf(w5, w5, rsq0);
                rsq1 = fmaf(w2, w2, rsq1); rsq1 = fmaf(w3, w3, rsq1);
                rsq1 = fmaf(w6, w6, rsq1); rsq1 = fmaf(w7, w7, rsq1);

                u32 wh[4];
                wh[0] = pack2h(w0, w1);
                wh[1] = pack2h(w2, w3);
                wh[2] = pack2h(w4, w5);
                wh[3] = pack2h(w6, w7);

                const int rV = 16 * t + rowVb;
                #pragma unroll
                for (int v = 0; v < 4; v++) {
                    u32 vh[4];
                    ldsm4t(vh, bb + 8192 + sw8(rV, 2 * v + cvb));
                    mma16816(o[2*v],   wh, vh);
                    mma16816(o[2*v+1], wh, vh + 2);
                }
            }
        }

        CP_WAIT0();
        __syncthreads();
    }

    rsq0 += __shfl_xor_sync(0xffffffffu, rsq0, 1);
    rsq0 += __shfl_xor_sync(0xffffffffu, rsq0, 2);
    rsq1 += __shfl_xor_sync(0xffffffffu, rsq1, 1);
    rsq1 += __shfl_xor_sync(0xffffffffu, rsq1, 2);
    const float inv0 = rsqrtf(rsq0);
    const float inv1 = rsqrtf(rsq1);

    const size_t obase = (size_t)(b * TT + qg0) * CC + h * 64 + 2 * tc;
    #pragma unroll
    for (int v = 0; v < 8; v++) {
        *(u32*)&att[obase + 8 * v] = pack2h(o[v][0] * inv0, o[v][1] * inv0);
        *(u32*)&att[obase + 8 * (size_t)CC + 8 * v] =
            pack2h(o[v][2] * inv1, o[v][3] * inv1);
    }
}

// ---------------------------------------------------------------------------
extern "C" void kernel_launch(void* const* d_in, const int* in_sizes, int n_in,
                              void* d_out, int out_size) {
    const float* x     = (const float*)d_in[0];
    const float* Wqkv  = (const float*)d_in[1];
    const float* Wproj = (const float*)d_in[2];
    const float* bproj = (const float*)d_in[3];
    float* out = (float*)d_out;

    __half *xh, *wq, *wp, *qkvp, *attp;
    cudaGetSymbolAddress((void**)&xh, g_x);
    cudaGetSymbolAddress((void**)&wq, g_wq);
    cudaGetSymbolAddress((void**)&wp, g_wp);
    cudaGetSymbolAddress((void**)&qkvp, g_qkv);
    cudaGetSymbolAddress((void**)&attp, g_att);

    cudaFuncSetAttribute(gemm_mma, cudaFuncAttributeMaxDynamicSharedMemorySize,
                         GM_SMEM_BYTES);
    cudaFuncSetAttribute(attn_mma, cudaFuncAttributeMaxDynamicSharedMemorySize,
                         AT_SMEM_BYTES);

    int n4x = BT * CC / 4;
    int n4q = 3 * CC * CC / 4;
    int n4p = CC * CC / 4;
    round_f16<<<(n4x + 255) / 256, 256>>>((const float4*)x, (uint2*)xh, n4x);
    round_f16<<<(n4q + 255) / 256, 256>>>((const float4*)Wqkv, (uint2*)wq, n4q);
    round_f16<<<(n4p + 255) / 256, 256>>>((const float4*)Wproj, (uint2*)wp, n4p);

    // 1) QKV = x @ Wqkv^T -> fp16
    gemm_mma<<<dim3((3 * CC) / 128, BT / 128), 256, GM_SMEM_BYTES>>>(
        xh, wq, nullptr, nullptr, qkvp, 3 * CC, CC);

    // 2) attention (causal sp2norm) -> fp16
    attn_mma<<<dim3(TT / 128, HH, BB), 256, AT_SMEM_BYTES>>>(qkvp, attp);

    // 3) out = att @ Wproj^T + b (fp32)
    gemm_mma<<<dim3(CC / 128, BT / 128), 256, GM_SMEM_BYTES>>>(
        attp, wp, bproj, out, nullptr, CC, CC);
}

// round 12
// speedup vs baseline: 2.6361x; 1.0286x over previous
#include <cuda_runtime.h>
#include <cuda_fp16.h>
#include <math.h>

#define BB 2
#define TT 2048
#define CC 1024
#define HH 16
#define BT (BB*TT)   // 4096

typedef unsigned int u32;
typedef unsigned long long u64;

// ---------------------------------------------------------------------------
// Scratch (__device__ globals; no allocations allowed)
// ---------------------------------------------------------------------------
__device__ __align__(256) __half g_x[(size_t)BT * CC];
__device__ __align__(256) __half g_wq[(size_t)3 * CC * CC];
__device__ __align__(256) __half g_wp[(size_t)CC * CC];
__device__ __align__(256) __half g_qkv[(size_t)BT * 3 * CC];
__device__ __align__(256) __half g_att[(size_t)BT * CC];

// ---------------------------------------------------------------------------
// PTX helpers
// ---------------------------------------------------------------------------
__device__ __forceinline__ u32 s2u(const void* p) {
    u32 a;
    asm("{ .reg .u64 t; cvta.to.shared.u64 t, %1; cvt.u32.u64 %0, t; }"
        : "=r"(a) : "l"(p));
    return a;
}
__device__ __forceinline__ void cpa16(u32 dst, const void* src) {
    asm volatile("cp.async.cg.shared.global [%0], [%1], 16;" :: "r"(dst), "l"(src));
}
#define CP_COMMIT() asm volatile("cp.async.commit_group;" ::: "memory")
#define CP_WAIT0()  asm volatile("cp.async.wait_group 0;" ::: "memory")
__device__ __forceinline__ void ldsm4(u32* r, u32 addr) {
    asm volatile("ldmatrix.sync.aligned.m8n8.x4.shared.b16 {%0,%1,%2,%3}, [%4];"
                 : "=r"(r[0]), "=r"(r[1]), "=r"(r[2]), "=r"(r[3]) : "r"(addr));
}
__device__ __forceinline__ void ldsm4t(u32* r, u32 addr) {
    asm volatile("ldmatrix.sync.aligned.m8n8.x4.trans.shared.b16 {%0,%1,%2,%3}, [%4];"
                 : "=r"(r[0]), "=r"(r[1]), "=r"(r[2]), "=r"(r[3]) : "r"(addr));
}
__device__ __forceinline__ void mma16816(float* d, const u32* a, const u32* b) {
    asm volatile(
        "mma.sync.aligned.m16n8k16.row.col.f32.f16.f16.f32 "
        "{%0,%1,%2,%3}, {%4,%5,%6,%7}, {%8,%9}, {%0,%1,%2,%3};"
        : "+f"(d[0]), "+f"(d[1]), "+f"(d[2]), "+f"(d[3])
        : "r"(a[0]), "r"(a[1]), "r"(a[2]), "r"(a[3]), "r"(b[0]), "r"(b[1]));
}
__device__ __forceinline__ u32 pack2h(float a, float b) {
    u32 d;
    asm("cvt.rn.f16x2.f32 %0, %1, %2;" : "=r"(d) : "f"(b), "f"(a));
    return d;
}
// softplus via fast exp + fast log (MUFU)
__device__ __forceinline__ float softplus_f(float x) {
    float e = __expf(-fabsf(x));
    return fmaxf(x, 0.f) + __logf(1.f + e);
}

// ---------------------------------------------------------------------------
// Fused fp32 -> fp16 rounding over the three inputs (one launch)
// ---------------------------------------------------------------------------
#define N4X (BT * CC / 4)           // 1,048,576
#define N4Q (3 * CC * CC / 4)       // 786,432
#define N4P (CC * CC / 4)           // 262,144
#define N4ALL (N4X + N4Q + N4P)

__global__ __launch_bounds__(256)
void round_all(const float4* __restrict__ x, const float4* __restrict__ wq,
               const float4* __restrict__ wp, uint2* __restrict__ dx,
               uint2* __restrict__ dwq, uint2* __restrict__ dwp) {
    int i = blockIdx.x * blockDim.x + threadIdx.x;
    const float4* s; uint2* d; int k;
    if (i < N4X)            { s = x;  d = dx;  k = i; }
    else if (i < N4X + N4Q) { s = wq; d = dwq; k = i - N4X; }
    else if (i < N4ALL)     { s = wp; d = dwp; k = i - N4X - N4Q; }
    else return;
    float4 v = s[k];
    d[k] = make_uint2(pack2h(v.x, v.y), pack2h(v.z, v.w));
}

// ---------------------------------------------------------------------------
// HMMA GEMM (fp16 1-term): C[M,N] = A[M,K] @ W[N,K]^T  (unchanged from R11)
// 128x128x64 tile, 8 warps (2m x 4n), double buffer, ONE sync/iter, 2 CTAs/SM.
// ---------------------------------------------------------------------------
#define GM_STAGE 32768
#define GM_SMEM_BYTES (2 * GM_STAGE)

__device__ __forceinline__ u32 sw8(int r, int c) {
    return (u32)(r * 128 + ((c ^ (r & 7)) << 4));
}

__device__ __forceinline__ void load_tile_g(
    u32 sbuf, int tid,
    const __half* __restrict__ A, const __half* __restrict__ W,
    int bm, int bn, int K, int k0)
{
    #pragma unroll
    for (int q = 0; q < 4; q++) {
        int idx = tid + q * 256;
        int r = idx >> 3;
        int c = idx & 7;
        u32 so = sw8(r, c);
        cpa16(sbuf +         so, A + (size_t)(bm + r) * K + k0 + c * 8);
        cpa16(sbuf + 16384 + so, W + (size_t)(bn + r) * K + k0 + c * 8);
    }
    CP_COMMIT();
}

__global__ __launch_bounds__(256, 2)
void gemm_mma(const __half* __restrict__ A, const __half* __restrict__ W,
              const float* __restrict__ bias, float* __restrict__ Cf,
              __half* __restrict__ Oh, int N, int K) {
    extern __shared__ char smem[];
    const u32 sb = s2u(smem);
    const int tid = threadIdx.x;
    const int wid = tid >> 5, lane = tid & 31;
    const int bm = blockIdx.y * 128, bn = blockIdx.x * 128;
    const int wm = (wid >> 2) * 64;
    const int wn = (wid & 3) * 32;

    float acc[4][4][4];
    #pragma unroll
    for (int i = 0; i < 4; i++)
        #pragma unroll
        for (int j = 0; j < 4; j++)
            #pragma unroll
            for (int u = 0; u < 4; u++) acc[i][j][u] = 0.f;

    const int NIT = K / 64;

    load_tile_g(sb, tid, A, W, bm, bn, K, 0);

    const int arow = lane & 15;
    const int akh  = lane >> 4;
    const int bj   = (lane >> 4) & 1;
    const int bkc  = (lane >> 3) & 1;
    const int brow = lane & 7;

    for (int it = 0; it < NIT; it++) {
        CP_WAIT0();
        __syncthreads();
        if (it + 1 < NIT) {
            load_tile_g(sb + ((it + 1) & 1) * GM_STAGE, tid,
                        A, W, bm, bn, K, (it + 1) * 64);
        }

        const u32 bb = sb + (it & 1) * GM_STAGE;
        #pragma unroll
        for (int kk2 = 0; kk2 < 8; kk2 += 2) {
            u32 ah[4][4];
            #pragma unroll
            for (int i = 0; i < 4; i++) {
                int row = wm + i * 16 + arow;
                ldsm4(ah[i], bb + sw8(row, kk2 + akh));
            }
            u32 wh4[2][4];
            #pragma unroll
            for (int jp = 0; jp < 2; jp++) {
                int row = wn + (jp * 2 + bj) * 8 + brow;
                ldsm4(wh4[jp], bb + 16384 + sw8(row, kk2 + bkc));
            }
            #pragma unroll
            for (int i = 0; i < 4; i++)
                #pragma unroll
                for (int j = 0; j < 4; j++)
                    mma16816(acc[i][j], ah[i], &wh4[j >> 1][(j & 1) * 2]);
        }
    }

    const int g = lane >> 2, tc = lane & 3;
    #pragma unroll
    for (int i = 0; i < 4; i++) {
        #pragma unroll
        for (int j = 0; j < 4; j++) {
            const int col = bn + wn + j * 8 + tc * 2;
            const size_t r0 = (size_t)(bm + wm + i * 16 + g) * N + col;
            const size_t r1 = r0 + (size_t)8 * N;
            if (Cf) {
                float b0 = bias ? bias[col] : 0.f;
                float b1 = bias ? bias[col + 1] : 0.f;
                *(float2*)&Cf[r0] = make_float2(acc[i][j][0] + b0, acc[i][j][1] + b1);
                *(float2*)&Cf[r1] = make_float2(acc[i][j][2] + b0, acc[i][j][3] + b1);
            } else {
                *(u32*)&Oh[r0] = pack2h(acc[i][j][0], acc[i][j][1]);
                *(u32*)&Oh[r1] = pack2h(acc[i][j][2], acc[i][j][3]);
            }
        }
    }
}

// ---------------------------------------------------------------------------
// HMMA sp2norm attention (fp16, 1-term). Paired-block loop: 4 KV ring
// buffers, 1 barrier per TWO 64-key blocks, 2 CTAs/SM. Q 16KB + 4x16KB.
// ---------------------------------------------------------------------------
#define AT_Q 0
#define AT_BUF 16384
#define AT_STAGE 16384
#define AT_SMEM_BYTES (16384 + 4 * AT_STAGE)

__device__ __forceinline__ void load_kv_a(
    u32 dst, int tid, const __half* __restrict__ qkv, size_t kvbase)
{
    #pragma unroll
    for (int q = 0; q < 2; q++) {
        int slot = tid + q * 256;
        int r = slot >> 3;
        int c = slot & 7;
        u32 so = sw8(r, c);
        size_t gk = kvbase + (size_t)r * (3 * CC) + CC + c * 8;
        cpa16(dst +        so, qkv + gk);        // K
        cpa16(dst + 8192 + so, qkv + gk + CC);   // V
    }
}

// Compute one 64-key block from KV buffer bb (device-inlined worker).
struct AttnState {
    float o[8][4];
    float rsq0, rsq1;
};

__device__ __forceinline__ void attn_block(
    const u32 bb, const u32 qh[4][4], AttnState& st,
    int lane, int tc, int j, int qb, int wid, int qg0)
{
    const bool dg = (j >= 2 * qb);
    if (dg && (j * 64 > qb * 128 + 16 * wid + 15)) return;   // fully masked strip

    float s[8][4];
    #pragma unroll
    for (int v = 0; v < 8; v++)
        #pragma unroll
        for (int u = 0; u < 4; u++) s[v][u] = 0.f;

    const int rowK = (lane & 7) + ((lane >> 4) << 3);
    const int ckK  = (lane >> 3) & 1;
    #pragma unroll
    for (int t = 0; t < 4; t++) {
        #pragma unroll
        for (int u = 0; u < 4; u++) {
            int rK = 16 * u + rowK;
            u32 kh[4];
            ldsm4(kh, bb + sw8(rK, 2 * t + ckK));
            mma16816(s[2*u],   qh[t], kh);
            mma16816(s[2*u+1], qh[t], kh + 2);
        }
    }

    const int rowVb = (lane & 7) + (((lane >> 3) & 1) << 3);
    const int cvb = lane >> 4;
    #pragma unroll
    for (int t = 0; t < 4; t++) {
        float w0 = softplus_f(s[2*t][0]   * 0.125f);
        float w1 = softplus_f(s[2*t][1]   * 0.125f);
        float w2 = softplus_f(s[2*t][2]   * 0.125f);
        float w3 = softplus_f(s[2*t][3]   * 0.125f);
        float w4 = softplus_f(s[2*t+1][0] * 0.125f);
        float w5 = softplus_f(s[2*t+1][1] * 0.125f);
        float w6 = softplus_f(s[2*t+1][2] * 0.125f);
        float w7 = softplus_f(s[2*t+1][3] * 0.125f);
        if (dg) {
            int kg = j * 64 + 16 * t + 2 * tc;
            int q0 = qg0, q1 = qg0 + 8;
            if (kg     > q0) w0 = 0.f;
            if (kg + 1 > q0) w1 = 0.f;
            if (kg     > q1) w2 = 0.f;
            if (kg + 1 > q1) w3 = 0.f;
            if (kg + 8 > q0) w4 = 0.f;
            if (kg + 9 > q0) w5 = 0.f;
            if (kg + 8 > q1) w6 = 0.f;
            if (kg + 9 > q1) w7 = 0.f;
        }
        st.rsq0 = fmaf(w0, w0, st.rsq0); st.rsq0 = fmaf(w1, w1, st.rsq0);
        st.rsq0 = fmaf(w4, w4, st.rsq0); st.rsq0 = fmaf(w5, w5, st.rsq0);
        st.rsq1 = fmaf(w2, w2, st.rsq1); st.rsq1 = fmaf(w3, w3, st.rsq1);
        st.rsq1 = fmaf(w6, w6, st.rsq1); st.rsq1 = fmaf(w7, w7, st.rsq1);

        u32 wh[4];
        wh[0] = pack2h(w0, w1);
        wh[1] = pack2h(w2, w3);
        wh[2] = pack2h(w4, w5);
        wh[3] = pack2h(w6, w7);

        const int rV = 16 * t + rowVb;
        #pragma unroll
        for (int v = 0; v < 4; v++) {
            u32 vh[4];
            ldsm4t(vh, bb + 8192 + sw8(rV, 2 * v + cvb));
            mma16816(st.o[2*v],   wh, vh);
            mma16816(st.o[2*v+1], wh, vh + 2);
        }
    }
}

__global__ __launch_bounds__(256, 2)
void attn_mma(const __half* __restrict__ qkv, __half* __restrict__ att) {
    extern __shared__ char smem[];
    const u32 sb = s2u(smem);
    const int tid = threadIdx.x;
    const int wid = tid >> 5, lane = tid & 31;
    const int g = lane >> 2, tc = lane & 3;
    const int qb = gridDim.x - 1 - blockIdx.x;
    const int h = blockIdx.y, b = blockIdx.z;

    const size_t qbase = ((size_t)(b * TT + qb * 128)) * (3 * CC) + h * 64;
    const size_t kvrow = ((size_t)(b * TT)) * (3 * CC) + h * 64;

    // Q tile + KV blocks 0,1 in ONE commit group
    #pragma unroll
    for (int q = 0; q < 4; q++) {
        int slot = tid + q * 256;
        int r = slot >> 3;
        int c = slot & 7;
        cpa16(sb + AT_Q + sw8(r, c), qkv + qbase + (size_t)r * (3 * CC) + c * 8);
    }
    load_kv_a(sb + AT_BUF,            tid, qkv, kvrow);
    load_kv_a(sb + AT_BUF + AT_STAGE, tid, qkv, kvrow + (size_t)64 * (3 * CC));
    CP_COMMIT();
    CP_WAIT0();
    __syncthreads();

    u32 qh[4][4];
    {
        const int row = 16 * wid + (lane & 15);
        const int ckb = lane >> 4;
        #pragma unroll
        for (int t = 0; t < 4; t++)
            ldsm4(qh[t], sb + AT_Q + sw8(row, 2 * t + ckb));
    }

    AttnState st;
    #pragma unroll
    for (int v = 0; v < 8; v++)
        #pragma unroll
        for (int u = 0; u < 4; u++) st.o[v][u] = 0.f;
    st.rsq0 = 0.f; st.rsq1 = 0.f;

    const int qg0 = qb * 128 + 16 * wid + g;
    const int jmax = 2 * qb + 1;   // odd -> block count even

    for (int jj = 0; jj <= jmax; jj += 2) {
        // prefetch pair (jj+2, jj+3)
        if (jj + 2 <= jmax) {
            load_kv_a(sb + AT_BUF + ((jj + 2) & 3) * AT_STAGE, tid, qkv,
                      kvrow + (size_t)((jj + 2) * 64) * (3 * CC));
            load_kv_a(sb + AT_BUF + ((jj + 3) & 3) * AT_STAGE, tid, qkv,
                      kvrow + (size_t)((jj + 3) * 64) * (3 * CC));
        }
        CP_COMMIT();

        attn_block(sb + AT_BUF + (jj & 3) * AT_STAGE, qh, st,
                   lane, tc, jj, qb, wid, qg0);
        attn_block(sb + AT_BUF + ((jj + 1) & 3) * AT_STAGE, qh, st,
                   lane, tc, jj + 1, qb, wid, qg0);

        CP_WAIT0();
        __syncthreads();
    }

    st.rsq0 += __shfl_xor_sync(0xffffffffu, st.rsq0, 1);
    st.rsq0 += __shfl_xor_sync(0xffffffffu, st.rsq0, 2);
    st.rsq1 += __shfl_xor_sync(0xffffffffu, st.rsq1, 1);
    st.rsq1 += __shfl_xor_sync(0xffffffffu, st.rsq1, 2);
    const float inv0 = rsqrtf(st.rsq0);
    const float inv1 = rsqrtf(st.rsq1);

    const size_t obase = (size_t)(b * TT + qg0) * CC + h * 64 + 2 * tc;
    #pragma unroll
    for (int v = 0; v < 8; v++) {
        *(u32*)&att[obase + 8 * v] = pack2h(st.o[v][0] * inv0, st.o[v][1] * inv0);
        *(u32*)&att[obase + 8 * (size_t)CC + 8 * v] =
            pack2h(st.o[v][2] * inv1, st.o[v][3] * inv1);
    }
}

// ---------------------------------------------------------------------------
extern "C" void kernel_launch(void* const* d_in, const int* in_sizes, int n_in,
                              void* d_out, int out_size) {
    const float* x     = (const float*)d_in[0];
    const float* Wqkv  = (const float*)d_in[1];
    const float* Wproj = (const float*)d_in[2];
    const float* bproj = (const float*)d_in[3];
    float* out = (float*)d_out;

    __half *xh, *wq, *wp, *qkvp, *attp;
    cudaGetSymbolAddress((void**)&xh, g_x);
    cudaGetSymbolAddress((void**)&wq, g_wq);
    cudaGetSymbolAddress((void**)&wp, g_wp);
    cudaGetSymbolAddress((void**)&qkvp, g_qkv);
    cudaGetSymbolAddress((void**)&attp, g_att);

    cudaFuncSetAttribute(gemm_mma, cudaFuncAttributeMaxDynamicSharedMemorySize,
                         GM_SMEM_BYTES);
    cudaFuncSetAttribute(attn_mma, cudaFuncAttributeMaxDynamicSharedMemorySize,
                         AT_SMEM_BYTES);

    // 0) round inputs to fp16 (single fused launch)
    round_all<<<(N4ALL + 255) / 256, 256>>>(
        (const float4*)x, (const float4*)Wqkv, (const float4*)Wproj,
        (uint2*)xh, (uint2*)wq, (uint2*)wp);

    // 1) QKV = x @ Wqkv^T -> fp16
    gemm_mma<<<dim3((3 * CC) / 128, BT / 128), 256, GM_SMEM_BYTES>>>(
        xh, wq, nullptr, nullptr, qkvp, 3 * CC, CC);

    // 2) attention (causal sp2norm) -> fp16
    attn_mma<<<dim3(TT / 128, HH, BB), 256, AT_SMEM_BYTES>>>(qkvp, attp);

    // 3) out = att @ Wproj^T + b (fp32)
    gemm_mma<<<dim3(CC / 128, BT / 128), 256, GM_SMEM_BYTES>>>(
        attp, wp, bproj, out, nullptr, CC, CC);
}

// round 13
// speedup vs baseline: 2.6930x; 1.0216x over previous
#include <cuda_runtime.h>
#include <cuda_fp16.h>
#include <math.h>

#define BB 2
#define TT 2048
#define CC 1024
#define HH 16
#define BT (BB*TT)   // 4096

typedef unsigned int u32;
typedef unsigned long long u64;

// ---------------------------------------------------------------------------
// Scratch (__device__ globals; no allocations allowed)
// ---------------------------------------------------------------------------
__device__ __align__(256) __half g_x[(size_t)BT * CC];
__device__ __align__(256) __half g_wq[(size_t)3 * CC * CC];
__device__ __align__(256) __half g_wp[(size_t)CC * CC];
__device__ __align__(256) __half g_qkv[(size_t)BT * 3 * CC];
__device__ __align__(256) __half g_att[(size_t)BT * CC];

// ---------------------------------------------------------------------------
// PTX helpers
// ---------------------------------------------------------------------------
__device__ __forceinline__ u32 s2u(const void* p) {
    u32 a;
    asm("{ .reg .u64 t; cvta.to.shared.u64 t, %1; cvt.u32.u64 %0, t; }"
        : "=r"(a) : "l"(p));
    return a;
}
__device__ __forceinline__ void cpa16(u32 dst, const void* src) {
    asm volatile("cp.async.cg.shared.global [%0], [%1], 16;" :: "r"(dst), "l"(src));
}
#define CP_COMMIT() asm volatile("cp.async.commit_group;" ::: "memory")
#define CP_WAIT0()  asm volatile("cp.async.wait_group 0;" ::: "memory")
__device__ __forceinline__ void ldsm4(u32* r, u32 addr) {
    asm volatile("ldmatrix.sync.aligned.m8n8.x4.shared.b16 {%0,%1,%2,%3}, [%4];"
                 : "=r"(r[0]), "=r"(r[1]), "=r"(r[2]), "=r"(r[3]) : "r"(addr));
}
__device__ __forceinline__ void ldsm4t(u32* r, u32 addr) {
    asm volatile("ldmatrix.sync.aligned.m8n8.x4.trans.shared.b16 {%0,%1,%2,%3}, [%4];"
                 : "=r"(r[0]), "=r"(r[1]), "=r"(r[2]), "=r"(r[3]) : "r"(addr));
}
__device__ __forceinline__ void mma16816(float* d, const u32* a, const u32* b) {
    asm volatile(
        "mma.sync.aligned.m16n8k16.row.col.f32.f16.f16.f32 "
        "{%0,%1,%2,%3}, {%4,%5,%6,%7}, {%8,%9}, {%0,%1,%2,%3};"
        : "+f"(d[0]), "+f"(d[1]), "+f"(d[2]), "+f"(d[3])
        : "r"(a[0]), "r"(a[1]), "r"(a[2]), "r"(a[3]), "r"(b[0]), "r"(b[1]));
}
// fp16-accumulate variant (2x rate): D/C are two f16x2 regs {d0,d1},{d2,d3}
__device__ __forceinline__ void mma16816h(u32* d, const u32* a, const u32* b) {
    asm volatile(
        "mma.sync.aligned.m16n8k16.row.col.f16.f16.f16.f16 "
        "{%0,%1}, {%2,%3,%4,%5}, {%6,%7}, {%0,%1};"
        : "+r"(d[0]), "+r"(d[1])
        : "r"(a[0]), "r"(a[1]), "r"(a[2]), "r"(a[3]), "r"(b[0]), "r"(b[1]));
}
__device__ __forceinline__ u32 pack2h(float a, float b) {
    u32 d;
    asm("cvt.rn.f16x2.f32 %0, %1, %2;" : "=r"(d) : "f"(b), "f"(a));
    return d;
}
// softplus via fast exp + fast log (MUFU)
__device__ __forceinline__ float softplus_f(float x) {
    float e = __expf(-fabsf(x));
    return fmaxf(x, 0.f) + __logf(1.f + e);
}

// ---------------------------------------------------------------------------
// Fused fp32 -> fp16 rounding over the three inputs (one launch)
// ---------------------------------------------------------------------------
#define N4X (BT * CC / 4)           // 1,048,576
#define N4Q (3 * CC * CC / 4)       // 786,432
#define N4P (CC * CC / 4)           // 262,144
#define N4ALL (N4X + N4Q + N4P)

__global__ __launch_bounds__(256)
void round_all(const float4* __restrict__ x, const float4* __restrict__ wq,
               const float4* __restrict__ wp, uint2* __restrict__ dx,
               uint2* __restrict__ dwq, uint2* __restrict__ dwp) {
    int i = blockIdx.x * blockDim.x + threadIdx.x;
    const float4* s; uint2* d; int k;
    if (i < N4X)            { s = x;  d = dx;  k = i; }
    else if (i < N4X + N4Q) { s = wq; d = dwq; k = i - N4X; }
    else if (i < N4ALL)     { s = wp; d = dwp; k = i - N4X - N4Q; }
    else return;
    float4 v = s[k];
    d[k] = make_uint2(pack2h(v.x, v.y), pack2h(v.z, v.w));
}

// ---------------------------------------------------------------------------
// HMMA GEMM (fp16 in, fp32 accum): C[M,N] = A[M,K] @ W[N,K]^T
// 128x128x64 tile, 8 warps (2m x 4n), double buffer, ONE sync/iter, 2 CTAs/SM.
// Oh-path epilogue scales by `oscale` when bn < oscale_ncols (Q pre-scale).
// ---------------------------------------------------------------------------
#define GM_STAGE 32768
#define GM_SMEM_BYTES (2 * GM_STAGE)

__device__ __forceinline__ u32 sw8(int r, int c) {
    return (u32)(r * 128 + ((c ^ (r & 7)) << 4));
}

__device__ __forceinline__ void load_tile_g(
    u32 sbuf, int tid,
    const __half* __restrict__ A, const __half* __restrict__ W,
    int bm, int bn, int K, int k0)
{
    #pragma unroll
    for (int q = 0; q < 4; q++) {
        int idx = tid + q * 256;
        int r = idx >> 3;
        int c = idx & 7;
        u32 so = sw8(r, c);
        cpa16(sbuf +         so, A + (size_t)(bm + r) * K + k0 + c * 8);
        cpa16(sbuf + 16384 + so, W + (size_t)(bn + r) * K + k0 + c * 8);
    }
    CP_COMMIT();
}

__global__ __launch_bounds__(256, 2)
void gemm_mma(const __half* __restrict__ A, const __half* __restrict__ W,
              const float* __restrict__ bias, float* __restrict__ Cf,
              __half* __restrict__ Oh, int N, int K,
              float oscale, int oscale_ncols) {
    extern __shared__ char smem[];
    const u32 sb = s2u(smem);
    const int tid = threadIdx.x;
    const int wid = tid >> 5, lane = tid & 31;
    const int bm = blockIdx.y * 128, bn = blockIdx.x * 128;
    const int wm = (wid >> 2) * 64;
    const int wn = (wid & 3) * 32;

    float acc[4][4][4];
    #pragma unroll
    for (int i = 0; i < 4; i++)
        #pragma unroll
        for (int j = 0; j < 4; j++)
            #pragma unroll
            for (int u = 0; u < 4; u++) acc[i][j][u] = 0.f;

    const int NIT = K / 64;

    load_tile_g(sb, tid, A, W, bm, bn, K, 0);

    const int arow = lane & 15;
    const int akh  = lane >> 4;
    const int bj   = (lane >> 4) & 1;
    const int bkc  = (lane >> 3) & 1;
    const int brow = lane & 7;

    for (int it = 0; it < NIT; it++) {
        CP_WAIT0();
        __syncthreads();
        if (it + 1 < NIT) {
            load_tile_g(sb + ((it + 1) & 1) * GM_STAGE, tid,
                        A, W, bm, bn, K, (it + 1) * 64);
        }

        const u32 bb = sb + (it & 1) * GM_STAGE;
        #pragma unroll
        for (int kk2 = 0; kk2 < 8; kk2 += 2) {
            u32 ah[4][4];
            #pragma unroll
            for (int i = 0; i < 4; i++) {
                int row = wm + i * 16 + arow;
                ldsm4(ah[i], bb + sw8(row, kk2 + akh));
            }
            u32 wh4[2][4];
            #pragma unroll
            for (int jp = 0; jp < 2; jp++) {
                int row = wn + (jp * 2 + bj) * 8 + brow;
                ldsm4(wh4[jp], bb + 16384 + sw8(row, kk2 + bkc));
            }
            #pragma unroll
            for (int i = 0; i < 4; i++)
                #pragma unroll
                for (int j = 0; j < 4; j++)
                    mma16816(acc[i][j], ah[i], &wh4[j >> 1][(j & 1) * 2]);
        }
    }

    const int g = lane >> 2, tc = lane & 3;
    const float sc = (bn < oscale_ncols) ? oscale : 1.0f;
    #pragma unroll
    for (int i = 0; i < 4; i++) {
        #pragma unroll
        for (int j = 0; j < 4; j++) {
            const int col = bn + wn + j * 8 + tc * 2;
            const size_t r0 = (size_t)(bm + wm + i * 16 + g) * N + col;
            const size_t r1 = r0 + (size_t)8 * N;
            if (Cf) {
                float b0 = bias ? bias[col] : 0.f;
                float b1 = bias ? bias[col + 1] : 0.f;
                *(float2*)&Cf[r0] = make_float2(acc[i][j][0] + b0, acc[i][j][1] + b1);
                *(float2*)&Cf[r1] = make_float2(acc[i][j][2] + b0, acc[i][j][3] + b1);
            } else {
                *(u32*)&Oh[r0] = pack2h(acc[i][j][0] * sc, acc[i][j][1] * sc);
                *(u32*)&Oh[r1] = pack2h(acc[i][j][2] * sc, acc[i][j][3] * sc);
            }
        }
    }
}

// ---------------------------------------------------------------------------
// HMMA sp2norm attention. S in fp16 accumulators (2x rate; Q pre-scaled by
// 1/8 so S partials are O(1)). WV in fp32 accum. Paired-block loop, 4 KV
// ring buffers, 1 barrier per two blocks, 2 CTAs/SM.
// ---------------------------------------------------------------------------
#define AT_Q 0
#define AT_BUF 16384
#define AT_STAGE 16384
#define AT_SMEM_BYTES (16384 + 4 * AT_STAGE)

__device__ __forceinline__ void load_kv_a(
    u32 dst, int tid, const __half* __restrict__ qkv, size_t kvbase)
{
    #pragma unroll
    for (int q = 0; q < 2; q++) {
        int slot = tid + q * 256;
        int r = slot >> 3;
        int c = slot & 7;
        u32 so = sw8(r, c);
        size_t gk = kvbase + (size_t)r * (3 * CC) + CC + c * 8;
        cpa16(dst +        so, qkv + gk);        // K
        cpa16(dst + 8192 + so, qkv + gk + CC);   // V
    }
}

struct AttnState {
    float o[8][4];
    float rsq0, rsq1;
};

__device__ __forceinline__ void attn_block(
    const u32 bb, const u32 qh[4][4], AttnState& st,
    int lane, int tc, int j, int qb, int wid, int qg0)
{
    const bool dg = (j >= 2 * qb);
    if (dg && (j * 64 > qb * 128 + 16 * wid + 15)) return;

    // S = Q K^T with fp16 accumulators: s2[v] = {d0,d1},{d2,d3}
    u32 s2[8][2];
    #pragma unroll
    for (int v = 0; v < 8; v++) { s2[v][0] = 0u; s2[v][1] = 0u; }

    const int rowK = (lane & 7) + ((lane >> 4) << 3);
    const int ckK  = (lane >> 3) & 1;
    #pragma unroll
    for (int t = 0; t < 4; t++) {
        #pragma unroll
        for (int u = 0; u < 4; u++) {
            int rK = 16 * u + rowK;
            u32 kh[4];
            ldsm4(kh, bb + sw8(rK, 2 * t + ckK));
            mma16816h(s2[2*u],   qh[t], kh);
            mma16816h(s2[2*u+1], qh[t], kh + 2);
        }
    }

    const int rowVb = (lane & 7) + (((lane >> 3) & 1) << 3);
    const int cvb = lane >> 4;
    #pragma unroll
    for (int t = 0; t < 4; t++) {
        float2 fa = __half22float2(*(const __half2*)&s2[2*t][0]);     // d0,d1 (row g)
        float2 fb = __half22float2(*(const __half2*)&s2[2*t][1]);     // d2,d3 (row g+8)
        float2 fc = __half22float2(*(const __half2*)&s2[2*t+1][0]);
        float2 fd = __half22float2(*(const __half2*)&s2[2*t+1][1]);
        float w0 = softplus_f(fa.x);
        float w1 = softplus_f(fa.y);
        float w2 = softplus_f(fb.x);
        float w3 = softplus_f(fb.y);
        float w4 = softplus_f(fc.x);
        float w5 = softplus_f(fc.y);
        float w6 = softplus_f(fd.x);
        float w7 = softplus_f(fd.y);
        if (dg) {
            int kg = j * 64 + 16 * t + 2 * tc;
            int q0 = qg0, q1 = qg0 + 8;
            if (kg     > q0) w0 = 0.f;
            if (kg + 1 > q0) w1 = 0.f;
            if (kg     > q1) w2 = 0.f;
            if (kg + 1 > q1) w3 = 0.f;
            if (kg + 8 > q0) w4 = 0.f;
            if (kg + 9 > q0) w5 = 0.f;
            if (kg + 8 > q1) w6 = 0.f;
            if (kg + 9 > q1) w7 = 0.f;
        }
        st.rsq0 = fmaf(w0, w0, st.rsq0); st.rsq0 = fmaf(w1, w1, st.rsq0);
        st.rsq0 = fmaf(w4, w4, st.rsq0); st.rsq0 = fmaf(w5, w5, st.rsq0);
        st.rsq1 = fmaf(w2, w2, st.rsq1); st.rsq1 = fmaf(w3, w3, st.rsq1);
        st.rsq1 = fmaf(w6, w6, st.rsq1); st.rsq1 = fmaf(w7, w7, st.rsq1);

        u32 wh[4];
        wh[0] = pack2h(w0, w1);
        wh[1] = pack2h(w2, w3);
        wh[2] = pack2h(w4, w5);
        wh[3] = pack2h(w6, w7);

        const int rV = 16 * t + rowVb;
        #pragma unroll
        for (int v = 0; v < 4; v++) {
            u32 vh[4];
            ldsm4t(vh, bb + 8192 + sw8(rV, 2 * v + cvb));
            mma16816(st.o[2*v],   wh, vh);
            mma16816(st.o[2*v+1], wh, vh + 2);
        }
    }
}

__global__ __launch_bounds__(256, 2)
void attn_mma(const __half* __restrict__ qkv, __half* __restrict__ att) {
    extern __shared__ char smem[];
    const u32 sb = s2u(smem);
    const int tid = threadIdx.x;
    const int wid = tid >> 5, lane = tid & 31;
    const int g = lane >> 2, tc = lane & 3;
    const int qb = gridDim.x - 1 - blockIdx.x;
    const int h = blockIdx.y, b = blockIdx.z;

    const size_t qbase = ((size_t)(b * TT + qb * 128)) * (3 * CC) + h * 64;
    const size_t kvrow = ((size_t)(b * TT)) * (3 * CC) + h * 64;

    #pragma unroll
    for (int q = 0; q < 4; q++) {
        int slot = tid + q * 256;
        int r = slot >> 3;
        int c = slot & 7;
        cpa16(sb + AT_Q + sw8(r, c), qkv + qbase + (size_t)r * (3 * CC) + c * 8);
    }
    load_kv_a(sb + AT_BUF,            tid, qkv, kvrow);
    load_kv_a(sb + AT_BUF + AT_STAGE, tid, qkv, kvrow + (size_t)64 * (3 * CC));
    CP_COMMIT();
    CP_WAIT0();
    __syncthreads();

    u32 qh[4][4];
    {
        const int row = 16 * wid + (lane & 15);
        const int ckb = lane >> 4;
        #pragma unroll
        for (int t = 0; t < 4; t++)
            ldsm4(qh[t], sb + AT_Q + sw8(row, 2 * t + ckb));
    }

    AttnState st;
    #pragma unroll
    for (int v = 0; v < 8; v++)
        #pragma unroll
        for (int u = 0; u < 4; u++) st.o[v][u] = 0.f;
    st.rsq0 = 0.f; st.rsq1 = 0.f;

    const int qg0 = qb * 128 + 16 * wid + g;
    const int jmax = 2 * qb + 1;   // odd -> even block count

    for (int jj = 0; jj <= jmax; jj += 2) {
        if (jj + 2 <= jmax) {
            load_kv_a(sb + AT_BUF + ((jj + 2) & 3) * AT_STAGE, tid, qkv,
                      kvrow + (size_t)((jj + 2) * 64) * (3 * CC));
            load_kv_a(sb + AT_BUF + ((jj + 3) & 3) * AT_STAGE, tid, qkv,
                      kvrow + (size_t)((jj + 3) * 64) * (3 * CC));
        }
        CP_COMMIT();

        attn_block(sb + AT_BUF + (jj & 3) * AT_STAGE, qh, st,
                   lane, tc, jj, qb, wid, qg0);
        attn_block(sb + AT_BUF + ((jj + 1) & 3) * AT_STAGE, qh, st,
                   lane, tc, jj + 1, qb, wid, qg0);

        CP_WAIT0();
        __syncthreads();
    }

    st.rsq0 += __shfl_xor_sync(0xffffffffu, st.rsq0, 1);
    st.rsq0 += __shfl_xor_sync(0xffffffffu, st.rsq0, 2);
    st.rsq1 += __shfl_xor_sync(0xffffffffu, st.rsq1, 1);
    st.rsq1 += __shfl_xor_sync(0xffffffffu, st.rsq1, 2);
    const float inv0 = rsqrtf(st.rsq0);
    const float inv1 = rsqrtf(st.rsq1);

    const size_t obase = (size_t)(b * TT + qg0) * CC + h * 64 + 2 * tc;
    #pragma unroll
    for (int v = 0; v < 8; v++) {
        *(u32*)&att[obase + 8 * v] = pack2h(st.o[v][0] * inv0, st.o[v][1] * inv0);
        *(u32*)&att[obase + 8 * (size_t)CC + 8 * v] =
            pack2h(st.o[v][2] * inv1, st.o[v][3] * inv1);
    }
}

// ---------------------------------------------------------------------------
extern "C" void kernel_launch(void* const* d_in, const int* in_sizes, int n_in,
                              void* d_out, int out_size) {
    const float* x     = (const float*)d_in[0];
    const float* Wqkv  = (const float*)d_in[1];
    const float* Wproj = (const float*)d_in[2];
    const float* bproj = (const float*)d_in[3];
    float* out = (float*)d_out;

    __half *xh, *wq, *wp, *qkvp, *attp;
    cudaGetSymbolAddress((void**)&xh, g_x);
    cudaGetSymbolAddress((void**)&wq, g_wq);
    cudaGetSymbolAddress((void**)&wp, g_wp);
    cudaGetSymbolAddress((void**)&qkvp, g_qkv);
    cudaGetSymbolAddress((void**)&attp, g_att);

    cudaFuncSetAttribute(gemm_mma, cudaFuncAttributeMaxDynamicSharedMemorySize,
                         GM_SMEM_BYTES);
    cudaFuncSetAttribute(attn_mma, cudaFuncAttributeMaxDynamicSharedMemorySize,
                         AT_SMEM_BYTES);

    // 0) round inputs to fp16 (single fused launch)
    round_all<<<(N4ALL + 255) / 256, 256>>>(
        (const float4*)x, (const float4*)Wqkv, (const float4*)Wproj,
        (uint2*)xh, (uint2*)wq, (uint2*)wp);

    // 1) QKV = x @ Wqkv^T -> fp16; Q columns (0..1023) pre-scaled by 1/8
    gemm_mma<<<dim3((3 * CC) / 128, BT / 128), 256, GM_SMEM_BYTES>>>(
        xh, wq, nullptr, nullptr, qkvp, 3 * CC, CC, 0.125f, CC);

    // 2) attention (causal sp2norm) -> fp16
    attn_mma<<<dim3(TT / 128, HH, BB), 256, AT_SMEM_BYTES>>>(qkvp, attp);

    // 3) out = att @ Wproj^T + b (fp32)
    gemm_mma<<<dim3(CC / 128, BT / 128), 256, GM_SMEM_BYTES>>>(
        attp, wp, bproj, out, nullptr, CC, CC, 1.0f, 0);
}